// round 1
// baseline (speedup 1.0000x reference)
#include <cuda_runtime.h>
#include <cstdio>

#define BQ 8
#define LQ 4096
#define DQ 512
#define D4Q 2048
#define MQ (BQ*LQ)          // 32768 rows
#define EPSQ 1e-5f

// ---------------- scratch (device globals: allocation-free) ----------------
__device__ __align__(128) float g_buf1[BQ*LQ*DQ];          // 64 MB
__device__ __align__(128) float g_buf2[BQ*LQ*DQ];          // 64 MB
__device__ __align__(128) float g_h[BQ*LQ*DQ];             // 64 MB
__device__ __align__(128) float g_t[BQ*LQ*D4Q];            // 256 MB (GELU intermediate)
__device__ __align__(128) float g_wt[15*DQ*DQ];            // transposed conv weights

// ---------------- weight transpose: W[o][c][k] -> wt[k][c][o] ----------------
__global__ void wtrans_kernel(float* __restrict__ dst, const float* __restrict__ src, int K) {
    int idx = blockIdx.x * blockDim.x + threadIdx.x;
    int tot = DQ * DQ * K;
    if (idx >= tot) return;
    int k = idx % K;
    int c = (idx / K) % DQ;
    int o = idx / (K * DQ);
    dst[k * DQ * DQ + c * DQ + o] = src[idx];
}

// ---------------- masked conv as tiled GEMM ----------------
// x layout (B, L, D); out layout (B, L, D).
// out[b,l,o] = bias[o] + sum_{k,c} mask(b,l,k) * x[b, l+k-PAD, c] * wt[k][c][o]
template<int K, int CC>
__global__ __launch_bounds__(256) void conv_kernel(
    const float* __restrict__ x, const int* __restrict__ chain,
    const float* __restrict__ wt, const float* __restrict__ bias,
    float* __restrict__ out)
{
    constexpr int BM = 128, BN = 128;
    constexpr int PAD = (K - 1) / 2;
    constexpr int RK = K * CC;
    constexpr int LDA = RK + 1;          // odd -> bank-conflict-free A frags

    extern __shared__ float smem[];
    float* As = smem;                    // [BM][LDA]
    float* Bs = As + BM * LDA;           // [RK][BN]
    int*   chs = (int*)(Bs + RK * BN);   // [BM + 2*PAD]

    const int b  = blockIdx.z;
    const int l0 = blockIdx.x * BM;
    const int o0 = blockIdx.y * BN;
    const int tid = threadIdx.x;
    const int tx = tid & 15, ty = tid >> 4;

    // chain window (OOB sentinel -1 never matches a real chain id 0..7)
    for (int i = tid; i < BM + 2 * PAD; i += 256) {
        int j = l0 + i - PAD;
        chs[i] = (j >= 0 && j < LQ) ? chain[b * LQ + j] : -1;
    }
    __syncthreads();

    float acc[8][8];
    {
        float bb[8];
        #pragma unroll
        for (int j = 0; j < 8; j++)
            bb[j] = bias[o0 + tx * 4 + (j & 3) + (j >> 2) * 64];
        #pragma unroll
        for (int i = 0; i < 8; i++)
            #pragma unroll
            for (int j = 0; j < 8; j++)
                acc[i][j] = bb[j];
    }

    const float* xb = x + (size_t)b * LQ * DQ;

    for (int c0 = 0; c0 < DQ; c0 += CC) {
        __syncthreads();
        // masked im2col tile: As[l][k*CC+c]
        for (int idx = tid; idx < BM * RK; idx += 256) {
            int l = idx / RK;
            int r = idx - l * RK;
            int k = r / CC;
            int c = r - k * CC;
            float v = 0.f;
            if (chs[l + k] == chs[l + PAD]) {
                int j = l0 + l + k - PAD;   // guaranteed in [0,L) when mask true
                v = xb[(size_t)j * DQ + c0 + c];
            }
            As[l * LDA + r] = v;
        }
        // weight tile: Bs[k*CC+c][o]
        for (int idx = tid; idx < RK * BN; idx += 256) {
            int r = idx / BN;
            int o = idx - r * BN;
            int k = r / CC;
            int c = r - k * CC;
            Bs[idx] = wt[k * DQ * DQ + (c0 + c) * DQ + o0 + o];
        }
        __syncthreads();

        #pragma unroll 8
        for (int r = 0; r < RK; r++) {
            float a[8];
            #pragma unroll
            for (int i = 0; i < 8; i++) a[i] = As[(ty * 8 + i) * LDA + r];
            float4 b0 = *(const float4*)(Bs + r * BN + tx * 4);
            float4 b1 = *(const float4*)(Bs + r * BN + 64 + tx * 4);
            float bb[8] = {b0.x, b0.y, b0.z, b0.w, b1.x, b1.y, b1.z, b1.w};
            #pragma unroll
            for (int i = 0; i < 8; i++)
                #pragma unroll
                for (int j = 0; j < 8; j++)
                    acc[i][j] += a[i] * bb[j];
        }
    }

    float* ob = out + (size_t)b * LQ * DQ;
    #pragma unroll
    for (int i = 0; i < 8; i++) {
        int l = l0 + ty * 8 + i;
        float4 v0 = make_float4(acc[i][0], acc[i][1], acc[i][2], acc[i][3]);
        float4 v1 = make_float4(acc[i][4], acc[i][5], acc[i][6], acc[i][7]);
        *(float4*)(ob + (size_t)l * DQ + o0 + tx * 4) = v0;
        *(float4*)(ob + (size_t)l * DQ + o0 + 64 + tx * 4) = v1;
    }
}

// ---------------- GELU (tanh approximation, matches jax.nn.gelu default) ----------------
__device__ __forceinline__ float gelu_tanh(float v) {
    float v3 = v * v * v;
    return 0.5f * v * (1.f + tanhf(0.7978845608028654f * (v + 0.044715f * v3)));
}

// ---------------- SGEMM: C = epi(A @ B + bias) ----------------
// A: MxKd row-major, B: KdxN row-major. EPI==0: bias+gelu ; EPI==1: bias only
template<int EPI>
__global__ __launch_bounds__(256) void sgemm_kernel(
    const float* __restrict__ A, const float* __restrict__ Bm,
    const float* __restrict__ bias, float* __restrict__ Cm,
    int M, int N, int Kd)
{
    constexpr int BM = 128, BN = 128, BK = 16, LDA = BK + 1;
    __shared__ float As[BM * LDA];
    __shared__ float Bs[BK * BN];

    const int m0 = blockIdx.x * BM;
    const int n0 = blockIdx.y * BN;
    const int tid = threadIdx.x;
    const int tx = tid & 15, ty = tid >> 4;

    float acc[8][8];
    #pragma unroll
    for (int i = 0; i < 8; i++)
        #pragma unroll
        for (int j = 0; j < 8; j++) acc[i][j] = 0.f;

    for (int k0 = 0; k0 < Kd; k0 += BK) {
        __syncthreads();
        for (int idx = tid; idx < BM * BK; idx += 256) {
            int l = idx / BK;
            int r = idx - l * BK;
            As[l * LDA + r] = A[(size_t)(m0 + l) * Kd + k0 + r];
        }
        for (int idx = tid; idx < BK * BN; idx += 256) {
            int r = idx / BN;
            int o = idx - r * BN;
            Bs[idx] = Bm[(size_t)(k0 + r) * N + n0 + o];
        }
        __syncthreads();

        #pragma unroll
        for (int r = 0; r < BK; r++) {
            float a[8];
            #pragma unroll
            for (int i = 0; i < 8; i++) a[i] = As[(ty * 8 + i) * LDA + r];
            float4 b0 = *(const float4*)(Bs + r * BN + tx * 4);
            float4 b1 = *(const float4*)(Bs + r * BN + 64 + tx * 4);
            float bb[8] = {b0.x, b0.y, b0.z, b0.w, b1.x, b1.y, b1.z, b1.w};
            #pragma unroll
            for (int i = 0; i < 8; i++)
                #pragma unroll
                for (int j = 0; j < 8; j++)
                    acc[i][j] += a[i] * bb[j];
        }
    }

    float bb[8];
    #pragma unroll
    for (int j = 0; j < 8; j++)
        bb[j] = bias[n0 + tx * 4 + (j & 3) + (j >> 2) * 64];

    #pragma unroll
    for (int i = 0; i < 8; i++) {
        int m = m0 + ty * 8 + i;
        float v[8];
        #pragma unroll
        for (int j = 0; j < 8; j++) {
            float u = acc[i][j] + bb[j];
            v[j] = (EPI == 0) ? gelu_tanh(u) : u;
        }
        float4 v0 = make_float4(v[0], v[1], v[2], v[3]);
        float4 v1 = make_float4(v[4], v[5], v[6], v[7]);
        *(float4*)(Cm + (size_t)m * N + n0 + tx * 4) = v0;
        *(float4*)(Cm + (size_t)m * N + n0 + 64 + tx * 4) = v1;
    }
}

// ---------------- fused residual + LayerNorm (row length D=512) ----------------
__global__ __launch_bounds__(128) void ln_kernel(
    const float* __restrict__ a, const float* __restrict__ r,
    const float* __restrict__ g, const float* __restrict__ beta,
    float* __restrict__ out)
{
    const int row = blockIdx.x;
    const int tid = threadIdx.x;           // 128 threads, 4 elems each
    const float4 va = ((const float4*)(a + (size_t)row * DQ))[tid];
    const float4 vb = ((const float4*)(r + (size_t)row * DQ))[tid];
    float v0 = va.x + vb.x, v1 = va.y + vb.y, v2 = va.z + vb.z, v3 = va.w + vb.w;

    float s  = v0 + v1 + v2 + v3;
    float sq = v0*v0 + v1*v1 + v2*v2 + v3*v3;
    #pragma unroll
    for (int off = 16; off; off >>= 1) {
        s  += __shfl_xor_sync(0xffffffffu, s,  off);
        sq += __shfl_xor_sync(0xffffffffu, sq, off);
    }
    __shared__ float ws[4], wq[4];
    if ((tid & 31) == 0) { ws[tid >> 5] = s; wq[tid >> 5] = sq; }
    __syncthreads();
    s  = ws[0] + ws[1] + ws[2] + ws[3];
    sq = wq[0] + wq[1] + wq[2] + wq[3];

    const float mu  = s * (1.f / DQ);
    const float var = sq * (1.f / DQ) - mu * mu;
    const float rs  = rsqrtf(var + EPSQ);

    const float4 g4 = ((const float4*)g)[tid];
    const float4 b4 = ((const float4*)beta)[tid];
    float4 o4;
    o4.x = (v0 - mu) * rs * g4.x + b4.x;
    o4.y = (v1 - mu) * rs * g4.y + b4.y;
    o4.z = (v2 - mu) * rs * g4.z + b4.z;
    o4.w = (v3 - mu) * rs * g4.w + b4.w;
    ((float4*)(out + (size_t)row * DQ))[tid] = o4;
}

// ---------------- launch ----------------
extern "C" void kernel_launch(void* const* d_in, const int* in_sizes, int n_in,
                              void* d_out, int out_size) {
    const float* x    = (const float*)d_in[0];
    const int*   chain= (const int*)  d_in[1];
    const float* W3   = (const float*)d_in[2];
    const float* b3   = (const float*)d_in[3];
    const float* W5   = (const float*)d_in[4];
    const float* b5   = (const float*)d_in[5];
    const float* W7   = (const float*)d_in[6];
    const float* b7   = (const float*)d_in[7];
    const float* w1   = (const float*)d_in[8];
    const float* bm1  = (const float*)d_in[9];
    const float* w2   = (const float*)d_in[10];
    const float* bm2  = (const float*)d_in[11];
    const float* g1   = (const float*)d_in[12];
    const float* be1  = (const float*)d_in[13];
    const float* g2   = (const float*)d_in[14];
    const float* be2  = (const float*)d_in[15];
    float* out = (float*)d_out;

    float *buf1, *buf2, *h, *t, *wt;
    cudaGetSymbolAddress((void**)&buf1, g_buf1);
    cudaGetSymbolAddress((void**)&buf2, g_buf2);
    cudaGetSymbolAddress((void**)&h,    g_h);
    cudaGetSymbolAddress((void**)&t,    g_t);
    cudaGetSymbolAddress((void**)&wt,   g_wt);

    // dynamic shared sizes per conv instance
    auto smem_sz = [](int K, int CC) {
        int RK = K * CC;
        return (size_t)(128 * (RK + 1) + RK * 128) * sizeof(float)
             + (size_t)(128 + (K - 1)) * sizeof(int);
    };
    const size_t s3 = smem_sz(3, 16), s5 = smem_sz(5, 16), s7 = smem_sz(7, 8);
    cudaFuncSetAttribute(conv_kernel<3,16>, cudaFuncAttributeMaxDynamicSharedMemorySize, (int)s3);
    cudaFuncSetAttribute(conv_kernel<5,16>, cudaFuncAttributeMaxDynamicSharedMemorySize, (int)s5);
    cudaFuncSetAttribute(conv_kernel<7, 8>, cudaFuncAttributeMaxDynamicSharedMemorySize, (int)s7);

    // 1) transpose conv weights into wt[k][c][o]
    wtrans_kernel<<<(DQ*DQ*3 + 255)/256, 256>>>(wt,              W3, 3);
    wtrans_kernel<<<(DQ*DQ*5 + 255)/256, 256>>>(wt + 3*DQ*DQ,    W5, 5);
    wtrans_kernel<<<(DQ*DQ*7 + 255)/256, 256>>>(wt + 8*DQ*DQ,    W7, 7);

    // 2) conv chain
    dim3 cgrid(LQ/128, DQ/128, BQ);
    conv_kernel<3,16><<<cgrid, 256, s3>>>(x,    chain, wt,           b3, buf1);
    conv_kernel<5,16><<<cgrid, 256, s5>>>(buf1, chain, wt + 3*DQ*DQ, b5, buf2);
    conv_kernel<7, 8><<<cgrid, 256, s7>>>(buf2, chain, wt + 8*DQ*DQ, b7, buf1);

    // 3) h = LN1(x + conv_out)
    ln_kernel<<<MQ, 128>>>(x, buf1, g1, be1, h);

    // 4) MLP
    sgemm_kernel<0><<<dim3(MQ/128, D4Q/128), 256>>>(h, w1, bm1, t,    MQ, D4Q, DQ);
    sgemm_kernel<1><<<dim3(MQ/128, DQ/128),  256>>>(t, w2, bm2, buf2, MQ, DQ,  D4Q);

    // 5) out = LN2(h + mlp)
    ln_kernel<<<MQ, 128>>>(h, buf2, g2, be2, out);
}

// round 3
// speedup vs baseline: 3.1033x; 3.1033x over previous
#include <cuda_runtime.h>
#include <cuda_bf16.h>
#include <cstdint>

#define BQ 8
#define LQ 4096
#define DQ 512
#define D4Q 2048
#define MQ (BQ*LQ)
#define EPSQ 1e-5f

// ======================= scratch (device globals) =======================
__device__ __align__(128) float g_buf1[MQ*DQ];
__device__ __align__(128) float g_buf2[MQ*DQ];
__device__ __align__(128) float g_h[MQ*DQ];
__device__ __align__(128) __nv_bfloat16 g_t_hi[(size_t)MQ*D4Q];
__device__ __align__(128) __nv_bfloat16 g_t_lo[(size_t)MQ*D4Q];
__device__ __align__(128) __nv_bfloat16 g_wc_hi[15*DQ*DQ];   // conv weights [tap][o][c]
__device__ __align__(128) __nv_bfloat16 g_wc_lo[15*DQ*DQ];
__device__ __align__(128) __nv_bfloat16 g_w1_hi[(size_t)D4Q*DQ];   // [o][c]
__device__ __align__(128) __nv_bfloat16 g_w1_lo[(size_t)D4Q*DQ];
__device__ __align__(128) __nv_bfloat16 g_w2_hi[(size_t)DQ*D4Q];   // [o][k]
__device__ __align__(128) __nv_bfloat16 g_w2_lo[(size_t)DQ*D4Q];

// ======================= small helpers =======================
__device__ __forceinline__ uint32_t smem_to_u32(const void* p) {
    uint32_t a;
    asm("{ .reg .u64 t; cvta.to.shared.u64 t, %1; cvt.u32.u64 %0, t; }" : "=r"(a) : "l"(p));
    return a;
}
#define LDSM4(r, addr) \
    asm volatile("ldmatrix.sync.aligned.m8n8.x4.shared.b16 {%0,%1,%2,%3}, [%4];" \
        : "=r"((r)[0]), "=r"((r)[1]), "=r"((r)[2]), "=r"((r)[3]) : "r"(addr))

__device__ __forceinline__ void mma_bf16(float* c, const uint32_t* a, uint32_t b0, uint32_t b1) {
    asm volatile(
        "mma.sync.aligned.m16n8k16.row.col.f32.bf16.bf16.f32 "
        "{%0,%1,%2,%3}, {%4,%5,%6,%7}, {%8,%9}, {%0,%1,%2,%3};"
        : "+f"(c[0]), "+f"(c[1]), "+f"(c[2]), "+f"(c[3])
        : "r"(a[0]), "r"(a[1]), "r"(a[2]), "r"(a[3]), "r"(b0), "r"(b1));
}

__device__ __forceinline__ void split_bf16(float v, __nv_bfloat16& hi, __nv_bfloat16& lo) {
    hi = __float2bfloat16_rn(v);
    lo = __float2bfloat16_rn(v - __bfloat162float(hi));
}
__device__ __forceinline__ float gelu_tanh(float v) {
    float v3 = v * v * v;
    return 0.5f * v * (1.f + tanhf(0.7978845608028654f * (v + 0.044715f * v3)));
}

// ======================= weight prep =======================
// conv W(o,c,k) -> dst[k][o][c]
__global__ void prep_conv(const float* __restrict__ W, __nv_bfloat16* __restrict__ hi,
                          __nv_bfloat16* __restrict__ lo, int K) {
    int idx = blockIdx.x * blockDim.x + threadIdx.x;
    int tot = DQ * DQ * K;
    if (idx >= tot) return;
    int k = idx % K;
    int c = (idx / K) % DQ;
    int o = idx / (K * DQ);
    size_t d = (size_t)k * DQ * DQ + (size_t)o * DQ + c;
    split_bf16(W[idx], hi[d], lo[d]);
}
// w1 (c,o) -> [o][c]
__global__ void prep_w1(const float* __restrict__ W, __nv_bfloat16* __restrict__ hi,
                        __nv_bfloat16* __restrict__ lo) {
    int idx = blockIdx.x * blockDim.x + threadIdx.x;
    if (idx >= DQ * D4Q) return;
    int c = idx / D4Q, o = idx % D4Q;
    size_t d = (size_t)o * DQ + c;
    split_bf16(W[idx], hi[d], lo[d]);
}
// w2 (k,o) -> [o][k]
__global__ void prep_w2(const float* __restrict__ W, __nv_bfloat16* __restrict__ hi,
                        __nv_bfloat16* __restrict__ lo) {
    int idx = blockIdx.x * blockDim.x + threadIdx.x;
    if (idx >= D4Q * DQ) return;
    int k = idx / DQ, o = idx % DQ;
    size_t d = (size_t)o * D4Q + k;
    split_bf16(W[idx], hi[d], lo[d]);
}

// ======================= warp-MMA GEMM =======================
// MODE 0: conv  — A = masked shifted x (fp32 -> bf16 hi/lo), out fp32 + bias
// MODE 1: mlp1  — A = h (fp32 -> hi/lo), out = gelu(acc+bias) -> bf16 hi/lo
// MODE 2: mlp2  — A = t_hi/t_lo (bf16 direct), out fp32 + bias
// CTA tile 128x128, BK=32; warp tile 32x64; 3-MMA hi/lo split.
template<int MODE, int KTAPS, int KTOT, int NOUT>
__global__ __launch_bounds__(256, 1) void gemm_mma(
    const float* __restrict__ Af,
    const __nv_bfloat16* __restrict__ Ahg, const __nv_bfloat16* __restrict__ Alg,
    const int* __restrict__ chain,
    const __nv_bfloat16* __restrict__ Bhg, const __nv_bfloat16* __restrict__ Blg,
    const float* __restrict__ bias,
    float* __restrict__ outf,
    __nv_bfloat16* __restrict__ ohg, __nv_bfloat16* __restrict__ olg)
{
    constexpr int PADC = (KTAPS - 1) / 2;
    constexpr int NCH  = (MODE == 0) ? KTAPS * (DQ / 32) : KTOT / 32;
    constexpr int LDS_ = 40;                 // 32 + 8 pad (80B stride)

    __shared__ __nv_bfloat16 Ah_s[128 * LDS_];
    __shared__ __nv_bfloat16 Al_s[128 * LDS_];
    __shared__ __nv_bfloat16 Bh_s[128 * LDS_];
    __shared__ __nv_bfloat16 Bl_s[128 * LDS_];
    __shared__ int chs[128 + 8];

    const int tid  = threadIdx.x;
    const int wid  = tid >> 5;
    const int lane = tid & 31;
    const int wm   = wid & 3;                // m-block of 32
    const int wn   = wid >> 2;               // n-block of 64
    const int bz   = blockIdx.z;
    const int l0   = blockIdx.x * 128;
    const int n0   = blockIdx.y * 128;
    const size_t arow0 = (MODE == 0) ? ((size_t)bz * LQ + l0) : (size_t)l0;

    const uint32_t smuAh = smem_to_u32(Ah_s);
    const uint32_t smuAl = smem_to_u32(Al_s);
    const uint32_t smuBh = smem_to_u32(Bh_s);
    const uint32_t smuBl = smem_to_u32(Bl_s);

    if (MODE == 0) {
        for (int i = tid; i < 128 + KTAPS - 1; i += 256) {
            int j = l0 + i - PADC;
            chs[i] = (j >= 0 && j < LQ) ? chain[bz * LQ + j] : -1;
        }
        __syncthreads();
    }

    const float* xa = (MODE == 0) ? (Af + (size_t)bz * LQ * DQ) : Af;

    float acc[2][8][4];
    #pragma unroll
    for (int i = 0; i < 2; i++)
        #pragma unroll
        for (int j = 0; j < 8; j++)
            #pragma unroll
            for (int q = 0; q < 4; q++) acc[i][j][q] = 0.f;

    // prefetch registers
    float4 aR[4];                 // MODE 0/1
    uint4  aH2[2], aL2[2];        // MODE 2
    uint4  bH2[2], bL2[2];

    auto loadTiles = [&](int ci) {
        // ---- B ----
        const int tap = (MODE == 0) ? (ci / (DQ / 32)) : 0;
        const int kc0 = (MODE == 0) ? ((ci % (DQ / 32)) * 32) : ci * 32;
        const size_t bofs = (MODE == 0) ? (size_t)tap * DQ * DQ : 0;
        #pragma unroll
        for (int i = 0; i < 2; i++) {
            int idx = tid + i * 256;         // 0..511
            int n = idx >> 2, q = idx & 3;
            size_t src = bofs + (size_t)(n0 + n) * KTOT + kc0 + q * 8;
            bH2[i] = *(const uint4*)(Bhg + src);
            bL2[i] = *(const uint4*)(Blg + src);
        }
        // ---- A ----
        if (MODE == 2) {
            const int k0 = ci * 32;
            #pragma unroll
            for (int i = 0; i < 2; i++) {
                int idx = tid + i * 256;
                int r = idx >> 2, q = idx & 3;
                size_t src = (arow0 + r) * (size_t)KTOT + k0 + q * 8;
                aH2[i] = *(const uint4*)(Ahg + src);
                aL2[i] = *(const uint4*)(Alg + src);
            }
        } else {
            const int c0 = (MODE == 0) ? ((ci % (DQ / 32)) * 32) : ci * 32;
            #pragma unroll
            for (int i = 0; i < 4; i++) {
                int idx = tid + i * 256;     // 0..1023
                int r = idx >> 3, q = idx & 7;
                bool ok = true;
                if (MODE == 0) ok = (chs[r + tap] == chs[r + PADC]);
                if (ok) {
                    size_t row = (MODE == 0) ? (size_t)(l0 + r + tap - PADC) : (arow0 + r);
                    aR[i] = *(const float4*)(xa + row * DQ + c0 + q * 4);
                } else {
                    aR[i] = make_float4(0.f, 0.f, 0.f, 0.f);
                }
            }
        }
    };

    auto storeTiles = [&]() {
        #pragma unroll
        for (int i = 0; i < 2; i++) {
            int idx = tid + i * 256;
            int n = idx >> 2, q = idx & 3;
            *(uint4*)&Bh_s[n * LDS_ + q * 8] = bH2[i];
            *(uint4*)&Bl_s[n * LDS_ + q * 8] = bL2[i];
        }
        if (MODE == 2) {
            #pragma unroll
            for (int i = 0; i < 2; i++) {
                int idx = tid + i * 256;
                int r = idx >> 2, q = idx & 3;
                *(uint4*)&Ah_s[r * LDS_ + q * 8] = aH2[i];
                *(uint4*)&Al_s[r * LDS_ + q * 8] = aL2[i];
            }
        } else {
            #pragma unroll
            for (int i = 0; i < 4; i++) {
                int idx = tid + i * 256;
                int r = idx >> 3, q = idx & 7;
                float4 v = aR[i];
                __nv_bfloat162 h0 = __floats2bfloat162_rn(v.x, v.y);
                __nv_bfloat162 h1 = __floats2bfloat162_rn(v.z, v.w);
                __nv_bfloat162 q0 = __floats2bfloat162_rn(v.x - __bfloat162float(h0.x),
                                                          v.y - __bfloat162float(h0.y));
                __nv_bfloat162 q1 = __floats2bfloat162_rn(v.z - __bfloat162float(h1.x),
                                                          v.w - __bfloat162float(h1.y));
                uint32_t* ph = (uint32_t*)&Ah_s[r * LDS_ + q * 4];
                uint32_t* pl = (uint32_t*)&Al_s[r * LDS_ + q * 4];
                ph[0] = *(uint32_t*)&h0; ph[1] = *(uint32_t*)&h1;
                pl[0] = *(uint32_t*)&q0; pl[1] = *(uint32_t*)&q1;
            }
        }
    };

    const int rsel = (lane & 7) + ((lane >> 3) & 1) * 8;
    const int ksel = (lane >> 4) * 8;

    loadTiles(0);
    for (int ci = 0; ci < NCH; ci++) {
        __syncthreads();
        storeTiles();
        __syncthreads();
        if (ci + 1 < NCH) loadTiles(ci + 1);

        #pragma unroll
        for (int ks = 0; ks < 2; ks++) {
            const int kb = ks * 16 + ksel;
            uint32_t af[2][2][4];
            uint32_t bf_[4][2][4];
            #pragma unroll
            for (int mi = 0; mi < 2; mi++) {
                uint32_t off = (uint32_t)(((wm * 32 + mi * 16 + rsel) * LDS_ + kb) * 2);
                LDSM4(af[mi][0], smuAh + off);
                LDSM4(af[mi][1], smuAl + off);
            }
            #pragma unroll
            for (int np = 0; np < 4; np++) {
                uint32_t off = (uint32_t)(((wn * 64 + np * 16 + rsel) * LDS_ + kb) * 2);
                LDSM4(bf_[np][0], smuBh + off);
                LDSM4(bf_[np][1], smuBl + off);
            }
            #pragma unroll
            for (int mi = 0; mi < 2; mi++)
                #pragma unroll
                for (int np = 0; np < 4; np++) {
                    float* c0 = acc[mi][np * 2];
                    float* c1 = acc[mi][np * 2 + 1];
                    mma_bf16(c0, af[mi][0], bf_[np][0][0], bf_[np][0][2]);
                    mma_bf16(c1, af[mi][0], bf_[np][0][1], bf_[np][0][3]);
                    mma_bf16(c0, af[mi][0], bf_[np][1][0], bf_[np][1][2]);
                    mma_bf16(c1, af[mi][0], bf_[np][1][1], bf_[np][1][3]);
                    mma_bf16(c0, af[mi][1], bf_[np][0][0], bf_[np][0][2]);
                    mma_bf16(c1, af[mi][1], bf_[np][0][1], bf_[np][0][3]);
                }
        }
    }

    // ---- epilogue (registers -> gmem) ----
    const int g = lane >> 2, t = lane & 3;
    #pragma unroll
    for (int mi = 0; mi < 2; mi++) {
        #pragma unroll
        for (int nj = 0; nj < 8; nj++) {
            const int col = n0 + wn * 64 + nj * 8 + t * 2;
            const size_t r0 = arow0 + wm * 32 + mi * 16 + g;
            const float b0v = bias[col], b1v = bias[col + 1];
            float u0 = acc[mi][nj][0] + b0v, u1 = acc[mi][nj][1] + b1v;
            float u2 = acc[mi][nj][2] + b0v, u3 = acc[mi][nj][3] + b1v;
            if (MODE == 1) {
                float g0 = gelu_tanh(u0), g1 = gelu_tanh(u1);
                float g2 = gelu_tanh(u2), g3 = gelu_tanh(u3);
                __nv_bfloat162 h01 = __floats2bfloat162_rn(g0, g1);
                __nv_bfloat162 l01 = __floats2bfloat162_rn(g0 - __bfloat162float(h01.x),
                                                           g1 - __bfloat162float(h01.y));
                __nv_bfloat162 h23 = __floats2bfloat162_rn(g2, g3);
                __nv_bfloat162 l23 = __floats2bfloat162_rn(g2 - __bfloat162float(h23.x),
                                                           g3 - __bfloat162float(h23.y));
                *(__nv_bfloat162*)(ohg + r0 * (size_t)NOUT + col)       = h01;
                *(__nv_bfloat162*)(olg + r0 * (size_t)NOUT + col)       = l01;
                *(__nv_bfloat162*)(ohg + (r0 + 8) * (size_t)NOUT + col) = h23;
                *(__nv_bfloat162*)(olg + (r0 + 8) * (size_t)NOUT + col) = l23;
            } else {
                *(float2*)(outf + r0 * (size_t)NOUT + col)       = make_float2(u0, u1);
                *(float2*)(outf + (r0 + 8) * (size_t)NOUT + col) = make_float2(u2, u3);
            }
        }
    }
}

// ======================= fused residual + LayerNorm =======================
__global__ __launch_bounds__(128) void ln_kernel(
    const float* __restrict__ a, const float* __restrict__ r,
    const float* __restrict__ g, const float* __restrict__ beta,
    float* __restrict__ out)
{
    const int row = blockIdx.x;
    const int tid = threadIdx.x;
    const float4 va = ((const float4*)(a + (size_t)row * DQ))[tid];
    const float4 vb = ((const float4*)(r + (size_t)row * DQ))[tid];
    float v0 = va.x + vb.x, v1 = va.y + vb.y, v2 = va.z + vb.z, v3 = va.w + vb.w;

    float s  = v0 + v1 + v2 + v3;
    float sq = v0*v0 + v1*v1 + v2*v2 + v3*v3;
    #pragma unroll
    for (int off = 16; off; off >>= 1) {
        s  += __shfl_xor_sync(0xffffffffu, s,  off);
        sq += __shfl_xor_sync(0xffffffffu, sq, off);
    }
    __shared__ float ws[4], wq[4];
    if ((tid & 31) == 0) { ws[tid >> 5] = s; wq[tid >> 5] = sq; }
    __syncthreads();
    s  = ws[0] + ws[1] + ws[2] + ws[3];
    sq = wq[0] + wq[1] + wq[2] + wq[3];

    const float mu  = s * (1.f / DQ);
    const float var = sq * (1.f / DQ) - mu * mu;
    const float rs  = rsqrtf(var + EPSQ);

    const float4 g4 = ((const float4*)g)[tid];
    const float4 b4 = ((const float4*)beta)[tid];
    float4 o4;
    o4.x = (v0 - mu) * rs * g4.x + b4.x;
    o4.y = (v1 - mu) * rs * g4.y + b4.y;
    o4.z = (v2 - mu) * rs * g4.z + b4.z;
    o4.w = (v3 - mu) * rs * g4.w + b4.w;
    ((float4*)(out + (size_t)row * DQ))[tid] = o4;
}

// ======================= launch =======================
extern "C" void kernel_launch(void* const* d_in, const int* in_sizes, int n_in,
                              void* d_out, int out_size) {
    const float* x    = (const float*)d_in[0];
    const int*   chain= (const int*)  d_in[1];
    const float* W3   = (const float*)d_in[2];
    const float* b3   = (const float*)d_in[3];
    const float* W5   = (const float*)d_in[4];
    const float* b5   = (const float*)d_in[5];
    const float* W7   = (const float*)d_in[6];
    const float* b7   = (const float*)d_in[7];
    const float* w1   = (const float*)d_in[8];
    const float* bm1  = (const float*)d_in[9];
    const float* w2   = (const float*)d_in[10];
    const float* bm2  = (const float*)d_in[11];
    const float* g1   = (const float*)d_in[12];
    const float* be1  = (const float*)d_in[13];
    const float* g2   = (const float*)d_in[14];
    const float* be2  = (const float*)d_in[15];
    float* out = (float*)d_out;

    float *buf1, *buf2, *h;
    __nv_bfloat16 *t_hi, *t_lo, *wch, *wcl, *w1h, *w1l, *w2h, *w2l;
    cudaGetSymbolAddress((void**)&buf1, g_buf1);
    cudaGetSymbolAddress((void**)&buf2, g_buf2);
    cudaGetSymbolAddress((void**)&h,    g_h);
    cudaGetSymbolAddress((void**)&t_hi, g_t_hi);
    cudaGetSymbolAddress((void**)&t_lo, g_t_lo);
    cudaGetSymbolAddress((void**)&wch,  g_wc_hi);
    cudaGetSymbolAddress((void**)&wcl,  g_wc_lo);
    cudaGetSymbolAddress((void**)&w1h,  g_w1_hi);
    cudaGetSymbolAddress((void**)&w1l,  g_w1_lo);
    cudaGetSymbolAddress((void**)&w2h,  g_w2_hi);
    cudaGetSymbolAddress((void**)&w2l,  g_w2_lo);

    // weight prep (bf16 hi/lo, transposed to [n][k])
    prep_conv<<<(DQ*DQ*3 + 255)/256, 256>>>(W3, wch,           wcl,           3);
    prep_conv<<<(DQ*DQ*5 + 255)/256, 256>>>(W5, wch + 3*DQ*DQ, wcl + 3*DQ*DQ, 5);
    prep_conv<<<(DQ*DQ*7 + 255)/256, 256>>>(W7, wch + 8*DQ*DQ, wcl + 8*DQ*DQ, 7);
    prep_w1<<<(DQ*D4Q + 255)/256, 256>>>(w1, w1h, w1l);
    prep_w2<<<(D4Q*DQ + 255)/256, 256>>>(w2, w2h, w2l);

    // conv chain
    dim3 cgrid(LQ/128, DQ/128, BQ);
    gemm_mma<0,3,DQ,DQ><<<cgrid, 256>>>(x,    nullptr, nullptr, chain, wch,           wcl,           b3, buf1, nullptr, nullptr);
    gemm_mma<0,5,DQ,DQ><<<cgrid, 256>>>(buf1, nullptr, nullptr, chain, wch + 3*DQ*DQ, wcl + 3*DQ*DQ, b5, buf2, nullptr, nullptr);
    gemm_mma<0,7,DQ,DQ><<<cgrid, 256>>>(buf2, nullptr, nullptr, chain, wch + 8*DQ*DQ, wcl + 8*DQ*DQ, b7, buf1, nullptr, nullptr);

    // h = LN1(x + conv)
    ln_kernel<<<MQ, 128>>>(x, buf1, g1, be1, h);

    // MLP
    gemm_mma<1,1,DQ,D4Q><<<dim3(MQ/128, D4Q/128, 1), 256>>>(h, nullptr, nullptr, nullptr, w1h, w1l, bm1, nullptr, t_hi, t_lo);
    gemm_mma<2,1,D4Q,DQ><<<dim3(MQ/128, DQ/128, 1),  256>>>(nullptr, t_hi, t_lo, nullptr, w2h, w2l, bm2, buf2, nullptr, nullptr);

    // out = LN2(h + mlp)
    ln_kernel<<<MQ, 128>>>(h, buf2, g2, be2, out);
}

// round 4
// speedup vs baseline: 3.4169x; 1.1011x over previous
#include <cuda_runtime.h>
#include <cuda_bf16.h>
#include <cstdint>

#define BQ 8
#define LQ 4096
#define DQ 512
#define D4Q 2048
#define MQ (BQ*LQ)
#define EPSQ 1e-5f

// ======================= scratch (device globals) =======================
__device__ __align__(128) __nv_bfloat16 g_x_hi[(size_t)MQ*DQ];
__device__ __align__(128) __nv_bfloat16 g_x_lo[(size_t)MQ*DQ];
__device__ __align__(128) __nv_bfloat16 g_c_hi[(size_t)MQ*DQ];
__device__ __align__(128) __nv_bfloat16 g_c_lo[(size_t)MQ*DQ];
__device__ __align__(128) __nv_bfloat16 g_d_hi[(size_t)MQ*DQ];
__device__ __align__(128) __nv_bfloat16 g_d_lo[(size_t)MQ*DQ];
__device__ __align__(128) __nv_bfloat16 g_h_hi[(size_t)MQ*DQ];
__device__ __align__(128) __nv_bfloat16 g_h_lo[(size_t)MQ*DQ];
__device__ __align__(128) __nv_bfloat16 g_t_hi[(size_t)MQ*D4Q];
__device__ __align__(128) __nv_bfloat16 g_t_lo[(size_t)MQ*D4Q];
__device__ __align__(128) float g_mlp[(size_t)MQ*DQ];
__device__ __align__(128) __nv_bfloat16 g_wc_hi[15*DQ*DQ];   // conv weights [tap][o][c]
__device__ __align__(128) __nv_bfloat16 g_wc_lo[15*DQ*DQ];
__device__ __align__(128) __nv_bfloat16 g_w1_hi[(size_t)D4Q*DQ];   // [o][c]
__device__ __align__(128) __nv_bfloat16 g_w1_lo[(size_t)D4Q*DQ];
__device__ __align__(128) __nv_bfloat16 g_w2_hi[(size_t)DQ*D4Q];   // [o][k]
__device__ __align__(128) __nv_bfloat16 g_w2_lo[(size_t)DQ*D4Q];

// ======================= small helpers =======================
__device__ __forceinline__ uint32_t smem_to_u32(const void* p) {
    uint32_t a;
    asm("{ .reg .u64 t; cvta.to.shared.u64 t, %1; cvt.u32.u64 %0, t; }" : "=r"(a) : "l"(p));
    return a;
}
#define LDSM4(r, addr) \
    asm volatile("ldmatrix.sync.aligned.m8n8.x4.shared.b16 {%0,%1,%2,%3}, [%4];" \
        : "=r"((r)[0]), "=r"((r)[1]), "=r"((r)[2]), "=r"((r)[3]) : "r"(addr))

__device__ __forceinline__ void mma_bf16(float* c, const uint32_t* a, uint32_t b0, uint32_t b1) {
    asm volatile(
        "mma.sync.aligned.m16n8k16.row.col.f32.bf16.bf16.f32 "
        "{%0,%1,%2,%3}, {%4,%5,%6,%7}, {%8,%9}, {%0,%1,%2,%3};"
        : "+f"(c[0]), "+f"(c[1]), "+f"(c[2]), "+f"(c[3])
        : "r"(a[0]), "r"(a[1]), "r"(a[2]), "r"(a[3]), "r"(b0), "r"(b1));
}
__device__ __forceinline__ void cp16(uint32_t dst, const void* src, bool pred) {
    int sz = pred ? 16 : 0;
    asm volatile("cp.async.cg.shared.global [%0], [%1], 16, %2;"
        :: "r"(dst), "l"(src), "r"(sz));
}
#define CP_COMMIT() asm volatile("cp.async.commit_group;" ::: "memory")
#define CP_WAIT1()  asm volatile("cp.async.wait_group 1;" ::: "memory")

__device__ __forceinline__ void split_bf16(float v, __nv_bfloat16& hi, __nv_bfloat16& lo) {
    hi = __float2bfloat16_rn(v);
    lo = __float2bfloat16_rn(v - __bfloat162float(hi));
}
__device__ __forceinline__ float gelu_tanh(float v) {
    float v3 = v * v * v;
    return 0.5f * v * (1.f + tanhf(0.7978845608028654f * (v + 0.044715f * v3)));
}

// ======================= prep kernels =======================
__global__ void prep_conv(const float* __restrict__ W, __nv_bfloat16* __restrict__ hi,
                          __nv_bfloat16* __restrict__ lo, int K) {
    int idx = blockIdx.x * blockDim.x + threadIdx.x;
    int tot = DQ * DQ * K;
    if (idx >= tot) return;
    int k = idx % K;
    int c = (idx / K) % DQ;
    int o = idx / (K * DQ);
    size_t d = (size_t)k * DQ * DQ + (size_t)o * DQ + c;
    split_bf16(W[idx], hi[d], lo[d]);
}
__global__ void prep_w1(const float* __restrict__ W, __nv_bfloat16* __restrict__ hi,
                        __nv_bfloat16* __restrict__ lo) {
    int idx = blockIdx.x * blockDim.x + threadIdx.x;
    if (idx >= DQ * D4Q) return;
    int c = idx / D4Q, o = idx % D4Q;
    size_t d = (size_t)o * DQ + c;
    split_bf16(W[idx], hi[d], lo[d]);
}
__global__ void prep_w2(const float* __restrict__ W, __nv_bfloat16* __restrict__ hi,
                        __nv_bfloat16* __restrict__ lo) {
    int idx = blockIdx.x * blockDim.x + threadIdx.x;
    if (idx >= D4Q * DQ) return;
    int k = idx / DQ, o = idx % DQ;
    size_t d = (size_t)o * D4Q + k;
    split_bf16(W[idx], hi[d], lo[d]);
}
// x fp32 -> hi/lo bf16
__global__ void convert_x(const float* __restrict__ x, __nv_bfloat16* __restrict__ hi,
                          __nv_bfloat16* __restrict__ lo) {
    size_t idx = (size_t)blockIdx.x * blockDim.x + threadIdx.x;
    float4 v = *(const float4*)(x + idx * 4);
    __nv_bfloat162 h0 = __floats2bfloat162_rn(v.x, v.y);
    __nv_bfloat162 h1 = __floats2bfloat162_rn(v.z, v.w);
    __nv_bfloat162 l0 = __floats2bfloat162_rn(v.x - __bfloat162float(h0.x),
                                              v.y - __bfloat162float(h0.y));
    __nv_bfloat162 l1 = __floats2bfloat162_rn(v.z - __bfloat162float(h1.x),
                                              v.w - __bfloat162float(h1.y));
    *(__nv_bfloat162*)(hi + idx * 4)     = h0;
    *(__nv_bfloat162*)(hi + idx * 4 + 2) = h1;
    *(__nv_bfloat162*)(lo + idx * 4)     = l0;
    *(__nv_bfloat162*)(lo + idx * 4 + 2) = l1;
}

// ======================= warp-MMA GEMM (cp.async 2-stage, BK=64) =======================
// All operands bf16 hi/lo in gmem.
// MODE 0: conv  — A masked/shifted; epilogue bias -> bf16 hi/lo out
// MODE 1: mlp1  — epilogue gelu(acc+bias) -> bf16 hi/lo out
// MODE 2: mlp2  — epilogue acc+bias -> fp32 out
template<int MODE, int KTAPS, int KTOT, int NOUT>
__global__ __launch_bounds__(256, 1) void gemm_mma(
    const __nv_bfloat16* __restrict__ Ahg, const __nv_bfloat16* __restrict__ Alg,
    const int* __restrict__ chain,
    const __nv_bfloat16* __restrict__ Bhg, const __nv_bfloat16* __restrict__ Blg,
    const float* __restrict__ bias,
    float* __restrict__ outf,
    __nv_bfloat16* __restrict__ ohg, __nv_bfloat16* __restrict__ olg)
{
    constexpr int PADC = (KTAPS - 1) / 2;
    constexpr int NCH  = (MODE == 0) ? KTAPS * (DQ / 64) : KTOT / 64;
    constexpr int LDS_ = 72;                       // 64 + 8 pad (144B row)
    constexpr uint32_t TILE  = 128 * LDS_ * 2;     // 18432 B
    constexpr uint32_t OFF_AH = 0, OFF_AL = TILE, OFF_BH = 2*TILE, OFF_BL = 3*TILE;
    constexpr uint32_t STAGE = 4 * TILE;           // 73728 B

    extern __shared__ __align__(128) char dyn[];
    __shared__ int chs[128 + 8];

    const int tid  = threadIdx.x;
    const int wid  = tid >> 5;
    const int lane = tid & 31;
    const int wm   = wid & 3;
    const int wn   = wid >> 2;
    const int bz   = blockIdx.z;
    const int l0   = blockIdx.x * 128;
    const int n0   = blockIdx.y * 128;
    const size_t arow0 = (MODE == 0) ? ((size_t)bz * LQ + l0) : (size_t)l0;
    const uint32_t smu = smem_to_u32(dyn);

    if (MODE == 0) {
        for (int i = tid; i < 128 + KTAPS - 1; i += 256) {
            int j = l0 + i - PADC;
            chs[i] = (j >= 0 && j < LQ) ? chain[bz * LQ + j] : -1;
        }
        __syncthreads();
    }

    float acc[2][8][4];
    #pragma unroll
    for (int i = 0; i < 2; i++)
        #pragma unroll
        for (int j = 0; j < 8; j++)
            #pragma unroll
            for (int q = 0; q < 4; q++) acc[i][j][q] = 0.f;

    auto issue_chunk = [&](int ci, int s) {
        const uint32_t sb = smu + s * STAGE;
        int tap = 0, k0;
        size_t bofs = 0;
        if (MODE == 0) { tap = ci >> 3; k0 = (ci & 7) * 64; bofs = (size_t)tap * DQ * DQ; }
        else k0 = ci * 64;
        #pragma unroll
        for (int i = 0; i < 4; i++) {           // B: 128 n-rows x 64k, hi+lo
            int idx = tid + i * 256;
            int n = idx >> 3, q = idx & 7;
            size_t src = bofs + (size_t)(n0 + n) * KTOT + k0 + q * 8;
            uint32_t doff = (uint32_t)((n * LDS_ + q * 8) * 2);
            cp16(sb + OFF_BH + doff, Bhg + src, true);
            cp16(sb + OFF_BL + doff, Blg + src, true);
        }
        #pragma unroll
        for (int i = 0; i < 4; i++) {           // A: 128 rows x 64k, hi+lo
            int idx = tid + i * 256;
            int r = idx >> 3, q = idx & 7;
            bool ok = true;
            size_t row;
            if (MODE == 0) {
                ok = (chs[r + tap] == chs[r + PADC]);
                int rr = l0 + r + tap - PADC;
                rr = rr < 0 ? 0 : (rr >= LQ ? LQ - 1 : rr);
                row = (size_t)bz * LQ + rr;
            } else {
                row = arow0 + r;
            }
            size_t src = row * (size_t)KTOT + k0 + q * 8;
            uint32_t doff = (uint32_t)((r * LDS_ + q * 8) * 2);
            cp16(sb + OFF_AH + doff, Ahg + src, ok);
            cp16(sb + OFF_AL + doff, Alg + src, ok);
        }
        CP_COMMIT();
    };

    const int rsel = (lane & 7) + ((lane >> 3) & 1) * 8;
    const int ksel = (lane >> 4) * 8;

    issue_chunk(0, 0);
    issue_chunk(1, 1);

    for (int ci = 0; ci < NCH; ci++) {
        const int s = ci & 1;
        CP_WAIT1();
        __syncthreads();

        const uint32_t sb = smu + s * STAGE;
        #pragma unroll
        for (int ks = 0; ks < 4; ks++) {
            const int kb = ks * 16 + ksel;
            uint32_t af[2][2][4];
            uint32_t bf_[4][2][4];
            #pragma unroll
            for (int mi = 0; mi < 2; mi++) {
                uint32_t off = (uint32_t)(((wm * 32 + mi * 16 + rsel) * LDS_ + kb) * 2);
                LDSM4(af[mi][0], sb + OFF_AH + off);
                LDSM4(af[mi][1], sb + OFF_AL + off);
            }
            #pragma unroll
            for (int np = 0; np < 4; np++) {
                uint32_t off = (uint32_t)(((wn * 64 + np * 16 + rsel) * LDS_ + kb) * 2);
                LDSM4(bf_[np][0], sb + OFF_BH + off);
                LDSM4(bf_[np][1], sb + OFF_BL + off);
            }
            #pragma unroll
            for (int mi = 0; mi < 2; mi++)
                #pragma unroll
                for (int np = 0; np < 4; np++) {
                    float* c0 = acc[mi][np * 2];
                    float* c1 = acc[mi][np * 2 + 1];
                    mma_bf16(c0, af[mi][0], bf_[np][0][0], bf_[np][0][2]);
                    mma_bf16(c1, af[mi][0], bf_[np][0][1], bf_[np][0][3]);
                    mma_bf16(c0, af[mi][0], bf_[np][1][0], bf_[np][1][2]);
                    mma_bf16(c1, af[mi][0], bf_[np][1][1], bf_[np][1][3]);
                    mma_bf16(c0, af[mi][1], bf_[np][0][0], bf_[np][0][2]);
                    mma_bf16(c1, af[mi][1], bf_[np][0][1], bf_[np][0][3]);
                }
        }
        __syncthreads();
        if (ci + 2 < NCH) issue_chunk(ci + 2, s);
        else CP_COMMIT();            // empty group keeps wait_group accounting aligned
    }

    // ---- epilogue ----
    const int g = lane >> 2, t = lane & 3;
    #pragma unroll
    for (int mi = 0; mi < 2; mi++) {
        #pragma unroll
        for (int nj = 0; nj < 8; nj++) {
            const int col = n0 + wn * 64 + nj * 8 + t * 2;
            const size_t r0 = arow0 + wm * 32 + mi * 16 + g;
            const float b0v = bias[col], b1v = bias[col + 1];
            float u0 = acc[mi][nj][0] + b0v, u1 = acc[mi][nj][1] + b1v;
            float u2 = acc[mi][nj][2] + b0v, u3 = acc[mi][nj][3] + b1v;
            if (MODE == 1) {
                u0 = gelu_tanh(u0); u1 = gelu_tanh(u1);
                u2 = gelu_tanh(u2); u3 = gelu_tanh(u3);
            }
            if (MODE == 2) {
                *(float2*)(outf + r0 * (size_t)NOUT + col)       = make_float2(u0, u1);
                *(float2*)(outf + (r0 + 8) * (size_t)NOUT + col) = make_float2(u2, u3);
            } else {
                __nv_bfloat162 h01 = __floats2bfloat162_rn(u0, u1);
                __nv_bfloat162 l01 = __floats2bfloat162_rn(u0 - __bfloat162float(h01.x),
                                                           u1 - __bfloat162float(h01.y));
                __nv_bfloat162 h23 = __floats2bfloat162_rn(u2, u3);
                __nv_bfloat162 l23 = __floats2bfloat162_rn(u2 - __bfloat162float(h23.x),
                                                           u3 - __bfloat162float(h23.y));
                *(__nv_bfloat162*)(ohg + r0 * (size_t)NOUT + col)       = h01;
                *(__nv_bfloat162*)(olg + r0 * (size_t)NOUT + col)       = l01;
                *(__nv_bfloat162*)(ohg + (r0 + 8) * (size_t)NOUT + col) = h23;
                *(__nv_bfloat162*)(olg + (r0 + 8) * (size_t)NOUT + col) = l23;
            }
        }
    }
}

// ======================= fused residual + LayerNorm =======================
// V=0: v = af + (rhi+rlo); out -> ohi/olo (bf16 split)
// V=1: v = (ahi+alo) + rf; out -> outf (fp32)
template<int V>
__global__ __launch_bounds__(128) void ln_kernel(
    const float* __restrict__ af,
    const __nv_bfloat16* __restrict__ ahi, const __nv_bfloat16* __restrict__ alo,
    const float* __restrict__ rf,
    const __nv_bfloat16* __restrict__ rhi, const __nv_bfloat16* __restrict__ rlo,
    const float* __restrict__ g, const float* __restrict__ beta,
    float* __restrict__ outf,
    __nv_bfloat16* __restrict__ ohi, __nv_bfloat16* __restrict__ olo)
{
    const int row = blockIdx.x;
    const int tid = threadIdx.x;
    const size_t base = (size_t)row * DQ + tid * 4;

    float v0, v1, v2, v3;
    if (V == 0) {
        const float4 va = *(const float4*)(af + base);
        __nv_bfloat162 h0 = *(const __nv_bfloat162*)(rhi + base);
        __nv_bfloat162 h1 = *(const __nv_bfloat162*)(rhi + base + 2);
        __nv_bfloat162 q0 = *(const __nv_bfloat162*)(rlo + base);
        __nv_bfloat162 q1 = *(const __nv_bfloat162*)(rlo + base + 2);
        v0 = va.x + __bfloat162float(h0.x) + __bfloat162float(q0.x);
        v1 = va.y + __bfloat162float(h0.y) + __bfloat162float(q0.y);
        v2 = va.z + __bfloat162float(h1.x) + __bfloat162float(q1.x);
        v3 = va.w + __bfloat162float(h1.y) + __bfloat162float(q1.y);
    } else {
        const float4 vr = *(const float4*)(rf + base);
        __nv_bfloat162 h0 = *(const __nv_bfloat162*)(ahi + base);
        __nv_bfloat162 h1 = *(const __nv_bfloat162*)(ahi + base + 2);
        __nv_bfloat162 q0 = *(const __nv_bfloat162*)(alo + base);
        __nv_bfloat162 q1 = *(const __nv_bfloat162*)(alo + base + 2);
        v0 = vr.x + __bfloat162float(h0.x) + __bfloat162float(q0.x);
        v1 = vr.y + __bfloat162float(h0.y) + __bfloat162float(q0.y);
        v2 = vr.z + __bfloat162float(h1.x) + __bfloat162float(q1.x);
        v3 = vr.w + __bfloat162float(h1.y) + __bfloat162float(q1.y);
    }

    float s  = v0 + v1 + v2 + v3;
    float sq = v0*v0 + v1*v1 + v2*v2 + v3*v3;
    #pragma unroll
    for (int off = 16; off; off >>= 1) {
        s  += __shfl_xor_sync(0xffffffffu, s,  off);
        sq += __shfl_xor_sync(0xffffffffu, sq, off);
    }
    __shared__ float ws[4], wq[4];
    if ((tid & 31) == 0) { ws[tid >> 5] = s; wq[tid >> 5] = sq; }
    __syncthreads();
    s  = ws[0] + ws[1] + ws[2] + ws[3];
    sq = wq[0] + wq[1] + wq[2] + wq[3];

    const float mu  = s * (1.f / DQ);
    const float var = sq * (1.f / DQ) - mu * mu;
    const float rs  = rsqrtf(var + EPSQ);

    const float4 g4 = ((const float4*)g)[tid];
    const float4 b4 = ((const float4*)beta)[tid];
    float o0 = (v0 - mu) * rs * g4.x + b4.x;
    float o1 = (v1 - mu) * rs * g4.y + b4.y;
    float o2 = (v2 - mu) * rs * g4.z + b4.z;
    float o3 = (v3 - mu) * rs * g4.w + b4.w;

    if (V == 0) {
        __nv_bfloat162 h01 = __floats2bfloat162_rn(o0, o1);
        __nv_bfloat162 l01 = __floats2bfloat162_rn(o0 - __bfloat162float(h01.x),
                                                   o1 - __bfloat162float(h01.y));
        __nv_bfloat162 h23 = __floats2bfloat162_rn(o2, o3);
        __nv_bfloat162 l23 = __floats2bfloat162_rn(o2 - __bfloat162float(h23.x),
                                                   o3 - __bfloat162float(h23.y));
        *(__nv_bfloat162*)(ohi + base)     = h01;
        *(__nv_bfloat162*)(ohi + base + 2) = h23;
        *(__nv_bfloat162*)(olo + base)     = l01;
        *(__nv_bfloat162*)(olo + base + 2) = l23;
    } else {
        *(float4*)(outf + base) = make_float4(o0, o1, o2, o3);
    }
}

// ======================= launch =======================
extern "C" void kernel_launch(void* const* d_in, const int* in_sizes, int n_in,
                              void* d_out, int out_size) {
    const float* x    = (const float*)d_in[0];
    const int*   chain= (const int*)  d_in[1];
    const float* W3   = (const float*)d_in[2];
    const float* b3   = (const float*)d_in[3];
    const float* W5   = (const float*)d_in[4];
    const float* b5   = (const float*)d_in[5];
    const float* W7   = (const float*)d_in[6];
    const float* b7   = (const float*)d_in[7];
    const float* w1   = (const float*)d_in[8];
    const float* bm1  = (const float*)d_in[9];
    const float* w2   = (const float*)d_in[10];
    const float* bm2  = (const float*)d_in[11];
    const float* g1   = (const float*)d_in[12];
    const float* be1  = (const float*)d_in[13];
    const float* g2   = (const float*)d_in[14];
    const float* be2  = (const float*)d_in[15];
    float* out = (float*)d_out;

    __nv_bfloat16 *xh, *xl, *ch, *cl, *dh, *dl, *hh, *hl, *th, *tl;
    __nv_bfloat16 *wch, *wcl, *w1h, *w1l, *w2h, *w2l;
    float* mlpf;
    cudaGetSymbolAddress((void**)&xh, g_x_hi);  cudaGetSymbolAddress((void**)&xl, g_x_lo);
    cudaGetSymbolAddress((void**)&ch, g_c_hi);  cudaGetSymbolAddress((void**)&cl, g_c_lo);
    cudaGetSymbolAddress((void**)&dh, g_d_hi);  cudaGetSymbolAddress((void**)&dl, g_d_lo);
    cudaGetSymbolAddress((void**)&hh, g_h_hi);  cudaGetSymbolAddress((void**)&hl, g_h_lo);
    cudaGetSymbolAddress((void**)&th, g_t_hi);  cudaGetSymbolAddress((void**)&tl, g_t_lo);
    cudaGetSymbolAddress((void**)&mlpf, g_mlp);
    cudaGetSymbolAddress((void**)&wch, g_wc_hi); cudaGetSymbolAddress((void**)&wcl, g_wc_lo);
    cudaGetSymbolAddress((void**)&w1h, g_w1_hi); cudaGetSymbolAddress((void**)&w1l, g_w1_lo);
    cudaGetSymbolAddress((void**)&w2h, g_w2_hi); cudaGetSymbolAddress((void**)&w2l, g_w2_lo);

    const int SMEMSZ = 2 * 4 * 128 * 72 * 2;   // 147456 B
    cudaFuncSetAttribute(gemm_mma<0,3,DQ,DQ>,  cudaFuncAttributeMaxDynamicSharedMemorySize, SMEMSZ);
    cudaFuncSetAttribute(gemm_mma<0,5,DQ,DQ>,  cudaFuncAttributeMaxDynamicSharedMemorySize, SMEMSZ);
    cudaFuncSetAttribute(gemm_mma<0,7,DQ,DQ>,  cudaFuncAttributeMaxDynamicSharedMemorySize, SMEMSZ);
    cudaFuncSetAttribute(gemm_mma<1,1,DQ,D4Q>, cudaFuncAttributeMaxDynamicSharedMemorySize, SMEMSZ);
    cudaFuncSetAttribute(gemm_mma<2,1,D4Q,DQ>, cudaFuncAttributeMaxDynamicSharedMemorySize, SMEMSZ);

    // prep
    prep_conv<<<(DQ*DQ*3 + 255)/256, 256>>>(W3, wch,           wcl,           3);
    prep_conv<<<(DQ*DQ*5 + 255)/256, 256>>>(W5, wch + 3*DQ*DQ, wcl + 3*DQ*DQ, 5);
    prep_conv<<<(DQ*DQ*7 + 255)/256, 256>>>(W7, wch + 8*DQ*DQ, wcl + 8*DQ*DQ, 7);
    prep_w1<<<(DQ*D4Q + 255)/256, 256>>>(w1, w1h, w1l);
    prep_w2<<<(D4Q*DQ + 255)/256, 256>>>(w2, w2h, w2l);
    convert_x<<<(MQ*DQ/4 + 255)/256, 256>>>(x, xh, xl);

    // conv chain
    dim3 cgrid(LQ/128, DQ/128, BQ);
    gemm_mma<0,3,DQ,DQ><<<cgrid, 256, SMEMSZ>>>(xh, xl, chain, wch,           wcl,           b3, nullptr, ch, cl);
    gemm_mma<0,5,DQ,DQ><<<cgrid, 256, SMEMSZ>>>(ch, cl, chain, wch + 3*DQ*DQ, wcl + 3*DQ*DQ, b5, nullptr, dh, dl);
    gemm_mma<0,7,DQ,DQ><<<cgrid, 256, SMEMSZ>>>(dh, dl, chain, wch + 8*DQ*DQ, wcl + 8*DQ*DQ, b7, nullptr, ch, cl);

    // h = LN1(x + conv)  -> bf16 hi/lo
    ln_kernel<0><<<MQ, 128>>>(x, nullptr, nullptr, nullptr, ch, cl, g1, be1, nullptr, hh, hl);

    // MLP
    gemm_mma<1,1,DQ,D4Q><<<dim3(MQ/128, D4Q/128, 1), 256, SMEMSZ>>>(hh, hl, nullptr, w1h, w1l, bm1, nullptr, th, tl);
    gemm_mma<2,1,D4Q,DQ><<<dim3(MQ/128, DQ/128, 1),  256, SMEMSZ>>>(th, tl, nullptr, w2h, w2l, bm2, mlpf, nullptr, nullptr);

    // out = LN2(h + mlp) -> fp32
    ln_kernel<1><<<MQ, 128>>>(nullptr, hh, hl, mlpf, nullptr, nullptr, g2, be2, out, nullptr, nullptr);
}

// round 6
// speedup vs baseline: 5.0395x; 1.4749x over previous
#include <cuda_runtime.h>
#include <cuda_fp16.h>
#include <cstdint>

#define BQ 8
#define LQ 4096
#define DQ 512
#define D4Q 2048
#define MQ (BQ*LQ)
#define EPSQ 1e-5f

// ======================= scratch (device globals) =======================
__device__ __align__(128) __half g_xa[(size_t)MQ*DQ];     // x as fp16
__device__ __align__(128) __half g_c1[(size_t)MQ*DQ];     // conv ping
__device__ __align__(128) __half g_c2[(size_t)MQ*DQ];     // conv pong
__device__ __align__(128) __half g_hh[(size_t)MQ*DQ];     // h fp16 (GEMM input)
__device__ __align__(128) float  g_hf[(size_t)MQ*DQ];     // h fp32 (LN2 residual)
__device__ __align__(128) __half g_t [(size_t)MQ*D4Q];    // GELU intermediate
__device__ __align__(128) float  g_mlp[(size_t)MQ*DQ];
__device__ __align__(128) __half g_wc_hi[15*DQ*DQ];       // conv W [tap][o][c]
__device__ __align__(128) __half g_wc_lo[15*DQ*DQ];
__device__ __align__(128) __half g_w1_hi[(size_t)D4Q*DQ]; // [o][c]
__device__ __align__(128) __half g_w1_lo[(size_t)D4Q*DQ];
__device__ __align__(128) __half g_w2_hi[(size_t)DQ*D4Q]; // [o][k]
__device__ __align__(128) __half g_w2_lo[(size_t)DQ*D4Q];

// ======================= helpers =======================
__device__ __forceinline__ uint32_t smem_to_u32(const void* p) {
    uint32_t a;
    asm("{ .reg .u64 t; cvta.to.shared.u64 t, %1; cvt.u32.u64 %0, t; }" : "=r"(a) : "l"(p));
    return a;
}
#define LDSM4(r, addr) \
    asm volatile("ldmatrix.sync.aligned.m8n8.x4.shared.b16 {%0,%1,%2,%3}, [%4];" \
        : "=r"((r)[0]), "=r"((r)[1]), "=r"((r)[2]), "=r"((r)[3]) : "r"(addr))

__device__ __forceinline__ void mma_f16(float* c, const uint32_t* a, uint32_t b0, uint32_t b1) {
    asm volatile(
        "mma.sync.aligned.m16n8k16.row.col.f32.f16.f16.f32 "
        "{%0,%1,%2,%3}, {%4,%5,%6,%7}, {%8,%9}, {%0,%1,%2,%3};"
        : "+f"(c[0]), "+f"(c[1]), "+f"(c[2]), "+f"(c[3])
        : "r"(a[0]), "r"(a[1]), "r"(a[2]), "r"(a[3]), "r"(b0), "r"(b1));
}
__device__ __forceinline__ void cp16(uint32_t dst, const void* src, bool pred) {
    int sz = pred ? 16 : 0;
    asm volatile("cp.async.cg.shared.global [%0], [%1], 16, %2;"
        :: "r"(dst), "l"(src), "r"(sz));
}
#define CP_COMMIT() asm volatile("cp.async.commit_group;" ::: "memory")
#define CP_WAIT1()  asm volatile("cp.async.wait_group 1;" ::: "memory")

__device__ __forceinline__ void split_f16(float v, __half& hi, __half& lo) {
    hi = __float2half_rn(v);
    lo = __float2half_rn(v - __half2float(hi));
}
__device__ __forceinline__ float gelu_tanh(float v) {
    float v3 = v * v * v;
    return 0.5f * v * (1.f + tanhf(0.7978845608028654f * (v + 0.044715f * v3)));
}

// ======================= prep kernels =======================
__global__ void prep_conv(const float* __restrict__ W, __half* __restrict__ hi,
                          __half* __restrict__ lo, int K) {
    int idx = blockIdx.x * blockDim.x + threadIdx.x;
    int tot = DQ * DQ * K;
    if (idx >= tot) return;
    int k = idx % K;
    int c = (idx / K) % DQ;
    int o = idx / (K * DQ);
    size_t d = (size_t)k * DQ * DQ + (size_t)o * DQ + c;
    split_f16(W[idx], hi[d], lo[d]);
}
__global__ void prep_w1(const float* __restrict__ W, __half* __restrict__ hi,
                        __half* __restrict__ lo) {
    int idx = blockIdx.x * blockDim.x + threadIdx.x;
    if (idx >= DQ * D4Q) return;
    int c = idx / D4Q, o = idx % D4Q;
    size_t d = (size_t)o * DQ + c;
    split_f16(W[idx], hi[d], lo[d]);
}
__global__ void prep_w2(const float* __restrict__ W, __half* __restrict__ hi,
                        __half* __restrict__ lo) {
    int idx = blockIdx.x * blockDim.x + threadIdx.x;
    if (idx >= D4Q * DQ) return;
    int k = idx / DQ, o = idx % DQ;
    size_t d = (size_t)o * D4Q + k;
    split_f16(W[idx], hi[d], lo[d]);
}
__global__ void convert_x(const float* __restrict__ x, __half* __restrict__ o) {
    size_t idx = (size_t)blockIdx.x * blockDim.x + threadIdx.x;
    float4 v = *(const float4*)(x + idx * 4);
    __half2 a = __floats2half2_rn(v.x, v.y);
    __half2 b = __floats2half2_rn(v.z, v.w);
    *(__half2*)(o + idx * 4)     = a;
    *(__half2*)(o + idx * 4 + 2) = b;
}

// ======================= warp-MMA GEMM (cp.async 2-stage, BK=128) =======================
// A fp16 single; B fp16 hi/lo; 2 MMAs per output pair.
// MODE 0: conv (masked A) -> fp16 out
// MODE 1: mlp1, gelu epilogue -> fp16 out
// MODE 2: mlp2 -> fp32 out
template<int MODE, int KTAPS, int KTOT, int NOUT>
__global__ __launch_bounds__(256, 1) void gemm_mma(
    const __half* __restrict__ Ag, const int* __restrict__ chain,
    const __half* __restrict__ Bhg, const __half* __restrict__ Blg,
    const float* __restrict__ bias,
    float* __restrict__ outf, __half* __restrict__ outh)
{
    constexpr int PADC = (KTAPS - 1) / 2;
    constexpr int NCH  = (MODE == 0) ? KTAPS * (DQ / 128) : KTOT / 128;
    constexpr int LDS_ = 136;                      // 128 + 8 pad (272B row)
    constexpr uint32_t TILE  = 128 * LDS_ * 2;     // 34816 B
    constexpr uint32_t OFF_A = 0, OFF_BH = TILE, OFF_BL = 2*TILE;
    constexpr uint32_t STAGE = 3 * TILE;           // 104448 B

    extern __shared__ __align__(128) char dyn[];
    __shared__ int chs[144];

    const int tid  = threadIdx.x;
    const int wid  = tid >> 5;
    const int lane = tid & 31;
    const int wm   = wid & 3;
    const int wn   = wid >> 2;
    const int bz   = blockIdx.z;
    const int l0   = blockIdx.x * 128;
    const int n0   = blockIdx.y * 128;
    const size_t arow0 = (MODE == 0) ? ((size_t)bz * LQ + l0) : (size_t)l0;
    const uint32_t smu = smem_to_u32(dyn);

    if (MODE == 0) {
        for (int i = tid; i < 128 + KTAPS - 1; i += 256) {
            int j = l0 + i - PADC;
            chs[i] = (j >= 0 && j < LQ) ? chain[bz * LQ + j] : -1;
        }
        __syncthreads();
    }

    float acc[2][8][4];
    #pragma unroll
    for (int i = 0; i < 2; i++)
        #pragma unroll
        for (int j = 0; j < 8; j++)
            #pragma unroll
            for (int q = 0; q < 4; q++) acc[i][j][q] = 0.f;

    auto issue_chunk = [&](int ci, int s) {
        const uint32_t sb = smu + s * STAGE;
        int tap = 0, k0;
        size_t bofs = 0;
        if (MODE == 0) { tap = ci >> 2; k0 = (ci & 3) * 128; bofs = (size_t)tap * DQ * DQ; }
        else k0 = ci * 128;
        #pragma unroll
        for (int i = 0; i < 8; i++) {          // B: 128 n-rows x 128 k, hi+lo
            int idx = tid + i * 256;
            int n = idx >> 4, q = idx & 15;
            size_t src = bofs + (size_t)(n0 + n) * KTOT + k0 + q * 8;
            uint32_t doff = (uint32_t)((n * LDS_ + q * 8) * 2);
            cp16(sb + OFF_BH + doff, Bhg + src, true);
            cp16(sb + OFF_BL + doff, Blg + src, true);
        }
        #pragma unroll
        for (int i = 0; i < 8; i++) {          // A: 128 rows x 128 k (single)
            int idx = tid + i * 256;
            int r = idx >> 4, q = idx & 15;
            bool ok = true;
            size_t row;
            if (MODE == 0) {
                ok = (chs[r + tap] == chs[r + PADC]);
                int rr = l0 + r + tap - PADC;
                rr = rr < 0 ? 0 : (rr >= LQ ? LQ - 1 : rr);
                row = (size_t)bz * LQ + rr;
            } else {
                row = arow0 + r;
            }
            size_t src = row * (size_t)KTOT + k0 + q * 8;
            cp16(sb + OFF_A + (uint32_t)((r * LDS_ + q * 8) * 2), Ag + src, ok);
        }
        CP_COMMIT();
    };

    const int rsel = (lane & 7) + ((lane >> 3) & 1) * 8;
    const int ksel = (lane >> 4) * 8;

    issue_chunk(0, 0);
    issue_chunk(1, 1);

    for (int ci = 0; ci < NCH; ci++) {
        const int s = ci & 1;
        CP_WAIT1();
        __syncthreads();

        const uint32_t sb = smu + s * STAGE;
        #pragma unroll
        for (int ks = 0; ks < 8; ks++) {
            const int kb = ks * 16 + ksel;
            uint32_t af[2][4];
            uint32_t bh[4][4], bl[4][4];
            #pragma unroll
            for (int mi = 0; mi < 2; mi++) {
                uint32_t off = (uint32_t)(((wm * 32 + mi * 16 + rsel) * LDS_ + kb) * 2);
                LDSM4(af[mi], sb + OFF_A + off);
            }
            #pragma unroll
            for (int np = 0; np < 4; np++) {
                uint32_t off = (uint32_t)(((wn * 64 + np * 16 + rsel) * LDS_ + kb) * 2);
                LDSM4(bh[np], sb + OFF_BH + off);
                LDSM4(bl[np], sb + OFF_BL + off);
            }
            #pragma unroll
            for (int mi = 0; mi < 2; mi++)
                #pragma unroll
                for (int np = 0; np < 4; np++) {
                    float* c0 = acc[mi][np * 2];
                    float* c1 = acc[mi][np * 2 + 1];
                    mma_f16(c0, af[mi], bh[np][0], bh[np][2]);
                    mma_f16(c1, af[mi], bh[np][1], bh[np][3]);
                    mma_f16(c0, af[mi], bl[np][0], bl[np][2]);
                    mma_f16(c1, af[mi], bl[np][1], bl[np][3]);
                }
        }
        __syncthreads();
        if (ci + 2 < NCH) issue_chunk(ci + 2, s);
        else CP_COMMIT();
    }

    // ---- epilogue ----
    const int g = lane >> 2, t = lane & 3;
    #pragma unroll
    for (int mi = 0; mi < 2; mi++) {
        #pragma unroll
        for (int nj = 0; nj < 8; nj++) {
            const int col = n0 + wn * 64 + nj * 8 + t * 2;
            const size_t r0 = arow0 + wm * 32 + mi * 16 + g;
            const float b0v = bias[col], b1v = bias[col + 1];
            float u0 = acc[mi][nj][0] + b0v, u1 = acc[mi][nj][1] + b1v;
            float u2 = acc[mi][nj][2] + b0v, u3 = acc[mi][nj][3] + b1v;
            if (MODE == 1) {
                u0 = gelu_tanh(u0); u1 = gelu_tanh(u1);
                u2 = gelu_tanh(u2); u3 = gelu_tanh(u3);
            }
            if (MODE == 2) {
                *(float2*)(outf + r0 * (size_t)NOUT + col)       = make_float2(u0, u1);
                *(float2*)(outf + (r0 + 8) * (size_t)NOUT + col) = make_float2(u2, u3);
            } else {
                *(__half2*)(outh + r0 * (size_t)NOUT + col)       = __floats2half2_rn(u0, u1);
                *(__half2*)(outh + (r0 + 8) * (size_t)NOUT + col) = __floats2half2_rn(u2, u3);
            }
        }
    }
}

// ======================= LN kernels =======================
// LN1: v = x(fp32) + conv(fp16); out -> h fp16 + h fp32
__global__ __launch_bounds__(128) void ln1_kernel(
    const float* __restrict__ x, const __half* __restrict__ cv,
    const float* __restrict__ g, const float* __restrict__ beta,
    __half* __restrict__ oh, float* __restrict__ of)
{
    const int row = blockIdx.x;
    const int tid = threadIdx.x;
    const size_t base = (size_t)row * DQ + tid * 4;

    const float4 va = *(const float4*)(x + base);
    __half2 c0 = *(const __half2*)(cv + base);
    __half2 c1 = *(const __half2*)(cv + base + 2);
    float v0 = va.x + __half2float(c0.x);
    float v1 = va.y + __half2float(c0.y);
    float v2 = va.z + __half2float(c1.x);
    float v3 = va.w + __half2float(c1.y);

    float s  = v0 + v1 + v2 + v3;
    float sq = v0*v0 + v1*v1 + v2*v2 + v3*v3;
    #pragma unroll
    for (int off = 16; off; off >>= 1) {
        s  += __shfl_xor_sync(0xffffffffu, s,  off);
        sq += __shfl_xor_sync(0xffffffffu, sq, off);
    }
    __shared__ float ws[4], wq[4];
    if ((tid & 31) == 0) { ws[tid >> 5] = s; wq[tid >> 5] = sq; }
    __syncthreads();
    s  = ws[0] + ws[1] + ws[2] + ws[3];
    sq = wq[0] + wq[1] + wq[2] + wq[3];

    const float mu  = s * (1.f / DQ);
    const float var = sq * (1.f / DQ) - mu * mu;
    const float rs  = rsqrtf(var + EPSQ);

    const float4 g4 = ((const float4*)g)[tid];
    const float4 b4 = ((const float4*)beta)[tid];
    float o0 = (v0 - mu) * rs * g4.x + b4.x;
    float o1 = (v1 - mu) * rs * g4.y + b4.y;
    float o2 = (v2 - mu) * rs * g4.z + b4.z;
    float o3 = (v3 - mu) * rs * g4.w + b4.w;

    *(__half2*)(oh + base)     = __floats2half2_rn(o0, o1);
    *(__half2*)(oh + base + 2) = __floats2half2_rn(o2, o3);
    *(float4*)(of + base) = make_float4(o0, o1, o2, o3);
}

// LN2: v = h(fp32) + mlp(fp32); out fp32
__global__ __launch_bounds__(128) void ln2_kernel(
    const float* __restrict__ h, const float* __restrict__ m,
    const float* __restrict__ g, const float* __restrict__ beta,
    float* __restrict__ out)
{
    const int row = blockIdx.x;
    const int tid = threadIdx.x;
    const size_t base = (size_t)row * DQ + tid * 4;

    const float4 va = *(const float4*)(h + base);
    const float4 vb = *(const float4*)(m + base);
    float v0 = va.x + vb.x, v1 = va.y + vb.y, v2 = va.z + vb.z, v3 = va.w + vb.w;

    float s  = v0 + v1 + v2 + v3;
    float sq = v0*v0 + v1*v1 + v2*v2 + v3*v3;
    #pragma unroll
    for (int off = 16; off; off >>= 1) {
        s  += __shfl_xor_sync(0xffffffffu, s,  off);
        sq += __shfl_xor_sync(0xffffffffu, sq, off);
    }
    __shared__ float ws[4], wq[4];
    if ((tid & 31) == 0) { ws[tid >> 5] = s; wq[tid >> 5] = sq; }
    __syncthreads();
    s  = ws[0] + ws[1] + ws[2] + ws[3];
    sq = wq[0] + wq[1] + wq[2] + wq[3];

    const float mu  = s * (1.f / DQ);
    const float var = sq * (1.f / DQ) - mu * mu;
    const float rs  = rsqrtf(var + EPSQ);

    const float4 g4 = ((const float4*)g)[tid];
    const float4 b4 = ((const float4*)beta)[tid];
    float4 o4;
    o4.x = (v0 - mu) * rs * g4.x + b4.x;
    o4.y = (v1 - mu) * rs * g4.y + b4.y;
    o4.z = (v2 - mu) * rs * g4.z + b4.z;
    o4.w = (v3 - mu) * rs * g4.w + b4.w;
    *(float4*)(out + base) = o4;
}

// ======================= launch =======================
extern "C" void kernel_launch(void* const* d_in, const int* in_sizes, int n_in,
                              void* d_out, int out_size) {
    const float* x    = (const float*)d_in[0];
    const int*   chain= (const int*)  d_in[1];
    const float* W3   = (const float*)d_in[2];
    const float* b3   = (const float*)d_in[3];
    const float* W5   = (const float*)d_in[4];
    const float* b5   = (const float*)d_in[5];
    const float* W7   = (const float*)d_in[6];
    const float* b7   = (const float*)d_in[7];
    const float* w1   = (const float*)d_in[8];
    const float* bm1  = (const float*)d_in[9];
    const float* w2   = (const float*)d_in[10];
    const float* bm2  = (const float*)d_in[11];
    const float* g1   = (const float*)d_in[12];
    const float* be1  = (const float*)d_in[13];
    const float* g2   = (const float*)d_in[14];
    const float* be2  = (const float*)d_in[15];
    float* out = (float*)d_out;

    __half *xa, *c1, *c2, *hh, *t, *wch, *wcl, *w1h, *w1l, *w2h, *w2l;
    float *hf, *mlpf;
    cudaGetSymbolAddress((void**)&xa, g_xa);
    cudaGetSymbolAddress((void**)&c1, g_c1);
    cudaGetSymbolAddress((void**)&c2, g_c2);
    cudaGetSymbolAddress((void**)&hh, g_hh);
    cudaGetSymbolAddress((void**)&hf, g_hf);
    cudaGetSymbolAddress((void**)&t,  g_t);
    cudaGetSymbolAddress((void**)&mlpf, g_mlp);
    cudaGetSymbolAddress((void**)&wch, g_wc_hi); cudaGetSymbolAddress((void**)&wcl, g_wc_lo);
    cudaGetSymbolAddress((void**)&w1h, g_w1_hi); cudaGetSymbolAddress((void**)&w1l, g_w1_lo);
    cudaGetSymbolAddress((void**)&w2h, g_w2_hi); cudaGetSymbolAddress((void**)&w2l, g_w2_lo);

    const int SMEMSZ = 2 * 3 * 128 * 136 * 2;   // 208896 B
    cudaFuncSetAttribute(gemm_mma<0,3,DQ,DQ>,  cudaFuncAttributeMaxDynamicSharedMemorySize, SMEMSZ);
    cudaFuncSetAttribute(gemm_mma<0,5,DQ,DQ>,  cudaFuncAttributeMaxDynamicSharedMemorySize, SMEMSZ);
    cudaFuncSetAttribute(gemm_mma<0,7,DQ,DQ>,  cudaFuncAttributeMaxDynamicSharedMemorySize, SMEMSZ);
    cudaFuncSetAttribute(gemm_mma<1,1,DQ,D4Q>, cudaFuncAttributeMaxDynamicSharedMemorySize, SMEMSZ);
    cudaFuncSetAttribute(gemm_mma<2,1,D4Q,DQ>, cudaFuncAttributeMaxDynamicSharedMemorySize, SMEMSZ);

    // prep
    prep_conv<<<(DQ*DQ*3 + 255)/256, 256>>>(W3, wch,           wcl,           3);
    prep_conv<<<(DQ*DQ*5 + 255)/256, 256>>>(W5, wch + 3*DQ*DQ, wcl + 3*DQ*DQ, 5);
    prep_conv<<<(DQ*DQ*7 + 255)/256, 256>>>(W7, wch + 8*DQ*DQ, wcl + 8*DQ*DQ, 7);
    prep_w1<<<(DQ*D4Q + 255)/256, 256>>>(w1, w1h, w1l);
    prep_w2<<<(D4Q*DQ + 255)/256, 256>>>(w2, w2h, w2l);
    convert_x<<<(MQ*DQ/4 + 255)/256, 256>>>(x, xa);

    // conv chain
    dim3 cgrid(LQ/128, DQ/128, BQ);
    gemm_mma<0,3,DQ,DQ><<<cgrid, 256, SMEMSZ>>>(xa, chain, wch,           wcl,           b3, nullptr, c1);
    gemm_mma<0,5,DQ,DQ><<<cgrid, 256, SMEMSZ>>>(c1, chain, wch + 3*DQ*DQ, wcl + 3*DQ*DQ, b5, nullptr, c2);
    gemm_mma<0,7,DQ,DQ><<<cgrid, 256, SMEMSZ>>>(c2, chain, wch + 8*DQ*DQ, wcl + 8*DQ*DQ, b7, nullptr, c1);

    // h = LN1(x + conv)
    ln1_kernel<<<MQ, 128>>>(x, c1, g1, be1, hh, hf);

    // MLP
    gemm_mma<1,1,DQ,D4Q><<<dim3(MQ/128, D4Q/128, 1), 256, SMEMSZ>>>(hh, nullptr, w1h, w1l, bm1, nullptr, t);
    gemm_mma<2,1,D4Q,DQ><<<dim3(MQ/128, DQ/128, 1),  256, SMEMSZ>>>(t,  nullptr, w2h, w2l, bm2, mlpf, nullptr);

    // out = LN2(h + mlp)
    ln2_kernel<<<MQ, 128>>>(hf, mlpf, g2, be2, out);
}

// round 8
// speedup vs baseline: 8.2626x; 1.6396x over previous
#include <cuda_runtime.h>
#include <cuda_fp16.h>
#include <cstdint>

#define BQ 8
#define LQ 4096
#define DQ 512
#define D4Q 2048
#define MQ (BQ*LQ)
#define EPSQ 1e-5f

// ======================= scratch (device globals) =======================
__device__ __align__(128) __half g_xa[(size_t)MQ*DQ];     // x as fp16
__device__ __align__(128) __half g_c1[(size_t)MQ*DQ];     // conv ping
__device__ __align__(128) __half g_c2[(size_t)MQ*DQ];     // conv pong
__device__ __align__(128) __half g_hh[(size_t)MQ*DQ];     // h fp16 (GEMM input)
__device__ __align__(128) float  g_hf[(size_t)MQ*DQ];     // h fp32 (LN2 residual)
__device__ __align__(128) __half g_t [(size_t)MQ*D4Q];    // GELU intermediate
__device__ __align__(128) float  g_mlp[(size_t)MQ*DQ];
__device__ __align__(128) __half g_wc[15*DQ*DQ];          // conv W [tap][o][c]
__device__ __align__(128) __half g_w1[(size_t)D4Q*DQ];    // [o][c]
__device__ __align__(128) __half g_w2[(size_t)DQ*D4Q];    // [o][k]

// ======================= helpers =======================
__device__ __forceinline__ uint32_t smem_to_u32(const void* p) {
    uint32_t a;
    asm("{ .reg .u64 t; cvta.to.shared.u64 t, %1; cvt.u32.u64 %0, t; }" : "=r"(a) : "l"(p));
    return a;
}
#define LDSM4(r, addr) \
    asm volatile("ldmatrix.sync.aligned.m8n8.x4.shared.b16 {%0,%1,%2,%3}, [%4];" \
        : "=r"((r)[0]), "=r"((r)[1]), "=r"((r)[2]), "=r"((r)[3]) : "r"(addr))

__device__ __forceinline__ void mma_f16(float* c, const uint32_t* a, uint32_t b0, uint32_t b1) {
    asm volatile(
        "mma.sync.aligned.m16n8k16.row.col.f32.f16.f16.f32 "
        "{%0,%1,%2,%3}, {%4,%5,%6,%7}, {%8,%9}, {%0,%1,%2,%3};"
        : "+f"(c[0]), "+f"(c[1]), "+f"(c[2]), "+f"(c[3])
        : "r"(a[0]), "r"(a[1]), "r"(a[2]), "r"(a[3]), "r"(b0), "r"(b1));
}
__device__ __forceinline__ void cp16(uint32_t dst, const void* src, bool pred) {
    int sz = pred ? 16 : 0;
    asm volatile("cp.async.cg.shared.global [%0], [%1], 16, %2;"
        :: "r"(dst), "l"(src), "r"(sz));
}
#define CP_COMMIT() asm volatile("cp.async.commit_group;" ::: "memory")
#define CP_WAIT2()  asm volatile("cp.async.wait_group 2;" ::: "memory")

__device__ __forceinline__ float gelu_tanh(float v) {
    float v3 = v * v * v;
    return 0.5f * v * (1.f + tanhf(0.7978845608028654f * (v + 0.044715f * v3)));
}

// ======================= prep kernels =======================
__global__ void prep_conv(const float* __restrict__ W, __half* __restrict__ o, int K) {
    int idx = blockIdx.x * blockDim.x + threadIdx.x;
    int tot = DQ * DQ * K;
    if (idx >= tot) return;
    int k = idx % K;
    int c = (idx / K) % DQ;
    int oo = idx / (K * DQ);
    o[(size_t)k * DQ * DQ + (size_t)oo * DQ + c] = __float2half_rn(W[idx]);
}
__global__ void prep_w1(const float* __restrict__ W, __half* __restrict__ o) {
    int idx = blockIdx.x * blockDim.x + threadIdx.x;
    if (idx >= DQ * D4Q) return;
    int c = idx / D4Q, oo = idx % D4Q;
    o[(size_t)oo * DQ + c] = __float2half_rn(W[idx]);
}
__global__ void prep_w2(const float* __restrict__ W, __half* __restrict__ o) {
    int idx = blockIdx.x * blockDim.x + threadIdx.x;
    if (idx >= D4Q * DQ) return;
    int k = idx / DQ, oo = idx % DQ;
    o[(size_t)oo * D4Q + k] = __float2half_rn(W[idx]);
}
__global__ void convert_x(const float* __restrict__ x, __half* __restrict__ o) {
    size_t idx = (size_t)blockIdx.x * blockDim.x + threadIdx.x;
    float4 v = *(const float4*)(x + idx * 4);
    *(__half2*)(o + idx * 4)     = __floats2half2_rn(v.x, v.y);
    *(__half2*)(o + idx * 4 + 2) = __floats2half2_rn(v.z, v.w);
}

// ======================= warp-MMA GEMM (cp.async 3-stage, BK=128) =======================
// A fp16, B fp16 (single); 1 MMA per output pair.
// MODE 0: conv (masked A) -> fp16 out
// MODE 1: mlp1, gelu epilogue -> fp16 out
// MODE 2: mlp2 -> fp32 out
template<int MODE, int KTAPS, int KTOT, int NOUT>
__global__ __launch_bounds__(256, 1) void gemm_mma(
    const __half* __restrict__ Ag, const int* __restrict__ chain,
    const __half* __restrict__ Bg,
    const float* __restrict__ bias,
    float* __restrict__ outf, __half* __restrict__ outh)
{
    constexpr int PADC = (KTAPS - 1) / 2;
    constexpr int NCH  = (MODE == 0) ? KTAPS * (DQ / 128) : KTOT / 128;
    constexpr int LDS_ = 136;                      // 128 + 8 pad (272B row)
    constexpr uint32_t TILE  = 128 * LDS_ * 2;     // 34816 B
    constexpr uint32_t OFF_A = 0, OFF_B = TILE;
    constexpr uint32_t STAGE = 2 * TILE;           // 69632 B

    extern __shared__ __align__(128) char dyn[];
    __shared__ int chs[144];

    const int tid  = threadIdx.x;
    const int wid  = tid >> 5;
    const int lane = tid & 31;
    const int wm   = wid & 3;
    const int wn   = wid >> 2;
    const int bz   = blockIdx.z;
    const int l0   = blockIdx.x * 128;
    const int n0   = blockIdx.y * 128;
    const size_t arow0 = (MODE == 0) ? ((size_t)bz * LQ + l0) : (size_t)l0;
    const uint32_t smu = smem_to_u32(dyn);

    if (MODE == 0) {
        for (int i = tid; i < 128 + KTAPS - 1; i += 256) {
            int j = l0 + i - PADC;
            chs[i] = (j >= 0 && j < LQ) ? chain[bz * LQ + j] : -1;
        }
        __syncthreads();
    }

    float acc[2][8][4];
    #pragma unroll
    for (int i = 0; i < 2; i++)
        #pragma unroll
        for (int j = 0; j < 8; j++)
            #pragma unroll
            for (int q = 0; q < 4; q++) acc[i][j][q] = 0.f;

    auto issue_chunk = [&](int ci, int s) {
        const uint32_t sb = smu + s * STAGE;
        int tap = 0, k0;
        size_t bofs = 0;
        if (MODE == 0) { tap = ci >> 2; k0 = (ci & 3) * 128; bofs = (size_t)tap * DQ * DQ; }
        else k0 = ci * 128;
        #pragma unroll
        for (int i = 0; i < 8; i++) {          // B: 128 n-rows x 128 k
            int idx = tid + i * 256;
            int n = idx >> 4, q = idx & 15;
            size_t src = bofs + (size_t)(n0 + n) * KTOT + k0 + q * 8;
            cp16(sb + OFF_B + (uint32_t)((n * LDS_ + q * 8) * 2), Bg + src, true);
        }
        #pragma unroll
        for (int i = 0; i < 8; i++) {          // A: 128 rows x 128 k
            int idx = tid + i * 256;
            int r = idx >> 4, q = idx & 15;
            bool ok = true;
            size_t row;
            if (MODE == 0) {
                ok = (chs[r + tap] == chs[r + PADC]);
                int rr = l0 + r + tap - PADC;
                rr = rr < 0 ? 0 : (rr >= LQ ? LQ - 1 : rr);
                row = (size_t)bz * LQ + rr;
            } else {
                row = arow0 + r;
            }
            size_t src = row * (size_t)KTOT + k0 + q * 8;
            cp16(sb + OFF_A + (uint32_t)((r * LDS_ + q * 8) * 2), Ag + src, ok);
        }
        CP_COMMIT();
    };

    const int rsel = (lane & 7) + ((lane >> 3) & 1) * 8;
    const int ksel = (lane >> 4) * 8;

    issue_chunk(0, 0);
    issue_chunk(1, 1);
    issue_chunk(2, 2);

    int s = 0;
    for (int ci = 0; ci < NCH; ci++) {
        CP_WAIT2();
        __syncthreads();

        const uint32_t sb = smu + s * STAGE;
        #pragma unroll
        for (int ks = 0; ks < 8; ks++) {
            const int kb = ks * 16 + ksel;
            uint32_t af[2][4];
            uint32_t bf[4][4];
            #pragma unroll
            for (int mi = 0; mi < 2; mi++) {
                uint32_t off = (uint32_t)(((wm * 32 + mi * 16 + rsel) * LDS_ + kb) * 2);
                LDSM4(af[mi], sb + OFF_A + off);
            }
            #pragma unroll
            for (int np = 0; np < 4; np++) {
                uint32_t off = (uint32_t)(((wn * 64 + np * 16 + rsel) * LDS_ + kb) * 2);
                LDSM4(bf[np], sb + OFF_B + off);
            }
            #pragma unroll
            for (int mi = 0; mi < 2; mi++)
                #pragma unroll
                for (int np = 0; np < 4; np++) {
                    mma_f16(acc[mi][np * 2],     af[mi], bf[np][0], bf[np][2]);
                    mma_f16(acc[mi][np * 2 + 1], af[mi], bf[np][1], bf[np][3]);
                }
        }
        __syncthreads();
        if (ci + 3 < NCH) issue_chunk(ci + 3, s);
        else CP_COMMIT();
        s = (s == 2) ? 0 : s + 1;
    }

    // ---- epilogue ----
    const int g = lane >> 2, t = lane & 3;
    #pragma unroll
    for (int mi = 0; mi < 2; mi++) {
        #pragma unroll
        for (int nj = 0; nj < 8; nj++) {
            const int col = n0 + wn * 64 + nj * 8 + t * 2;
            const size_t r0 = arow0 + wm * 32 + mi * 16 + g;
            const float b0v = bias[col], b1v = bias[col + 1];
            float u0 = acc[mi][nj][0] + b0v, u1 = acc[mi][nj][1] + b1v;
            float u2 = acc[mi][nj][2] + b0v, u3 = acc[mi][nj][3] + b1v;
            if (MODE == 1) {
                u0 = gelu_tanh(u0); u1 = gelu_tanh(u1);
                u2 = gelu_tanh(u2); u3 = gelu_tanh(u3);
            }
            if (MODE == 2) {
                *(float2*)(outf + r0 * (size_t)NOUT + col)       = make_float2(u0, u1);
                *(float2*)(outf + (r0 + 8) * (size_t)NOUT + col) = make_float2(u2, u3);
            } else {
                *(__half2*)(outh + r0 * (size_t)NOUT + col)       = __floats2half2_rn(u0, u1);
                *(__half2*)(outh + (r0 + 8) * (size_t)NOUT + col) = __floats2half2_rn(u2, u3);
            }
        }
    }
}

// ======================= LN kernels =======================
__global__ __launch_bounds__(128) void ln1_kernel(
    const float* __restrict__ x, const __half* __restrict__ cv,
    const float* __restrict__ g, const float* __restrict__ beta,
    __half* __restrict__ oh, float* __restrict__ of)
{
    const int row = blockIdx.x;
    const int tid = threadIdx.x;
    const size_t base = (size_t)row * DQ + tid * 4;

    const float4 va = *(const float4*)(x + base);
    __half2 c0 = *(const __half2*)(cv + base);
    __half2 c1 = *(const __half2*)(cv + base + 2);
    float v0 = va.x + __half2float(c0.x);
    float v1 = va.y + __half2float(c0.y);
    float v2 = va.z + __half2float(c1.x);
    float v3 = va.w + __half2float(c1.y);

    float s  = v0 + v1 + v2 + v3;
    float sq = v0*v0 + v1*v1 + v2*v2 + v3*v3;
    #pragma unroll
    for (int off = 16; off; off >>= 1) {
        s  += __shfl_xor_sync(0xffffffffu, s,  off);
        sq += __shfl_xor_sync(0xffffffffu, sq, off);
    }
    __shared__ float ws[4], wq[4];
    if ((tid & 31) == 0) { ws[tid >> 5] = s; wq[tid >> 5] = sq; }
    __syncthreads();
    s  = ws[0] + ws[1] + ws[2] + ws[3];
    sq = wq[0] + wq[1] + wq[2] + wq[3];

    const float mu  = s * (1.f / DQ);
    const float var = sq * (1.f / DQ) - mu * mu;
    const float rs  = rsqrtf(var + EPSQ);

    const float4 g4 = ((const float4*)g)[tid];
    const float4 b4 = ((const float4*)beta)[tid];
    float o0 = (v0 - mu) * rs * g4.x + b4.x;
    float o1 = (v1 - mu) * rs * g4.y + b4.y;
    float o2 = (v2 - mu) * rs * g4.z + b4.z;
    float o3 = (v3 - mu) * rs * g4.w + b4.w;

    *(__half2*)(oh + base)     = __floats2half2_rn(o0, o1);
    *(__half2*)(oh + base + 2) = __floats2half2_rn(o2, o3);
    *(float4*)(of + base) = make_float4(o0, o1, o2, o3);
}

__global__ __launch_bounds__(128) void ln2_kernel(
    const float* __restrict__ h, const float* __restrict__ m,
    const float* __restrict__ g, const float* __restrict__ beta,
    float* __restrict__ out)
{
    const int row = blockIdx.x;
    const int tid = threadIdx.x;
    const size_t base = (size_t)row * DQ + tid * 4;

    const float4 va = *(const float4*)(h + base);
    const float4 vb = *(const float4*)(m + base);
    float v0 = va.x + vb.x, v1 = va.y + vb.y, v2 = va.z + vb.z, v3 = va.w + vb.w;

    float s  = v0 + v1 + v2 + v3;
    float sq = v0*v0 + v1*v1 + v2*v2 + v3*v3;
    #pragma unroll
    for (int off = 16; off; off >>= 1) {
        s  += __shfl_xor_sync(0xffffffffu, s,  off);
        sq += __shfl_xor_sync(0xffffffffu, sq, off);
    }
    __shared__ float ws[4], wq[4];
    if ((tid & 31) == 0) { ws[tid >> 5] = s; wq[tid >> 5] = sq; }
    __syncthreads();
    s  = ws[0] + ws[1] + ws[2] + ws[3];
    sq = wq[0] + wq[1] + wq[2] + wq[3];

    const float mu  = s * (1.f / DQ);
    const float var = sq * (1.f / DQ) - mu * mu;
    const float rs  = rsqrtf(var + EPSQ);

    const float4 g4 = ((const float4*)g)[tid];
    const float4 b4 = ((const float4*)beta)[tid];
    float4 o4;
    o4.x = (v0 - mu) * rs * g4.x + b4.x;
    o4.y = (v1 - mu) * rs * g4.y + b4.y;
    o4.z = (v2 - mu) * rs * g4.z + b4.z;
    o4.w = (v3 - mu) * rs * g4.w + b4.w;
    *(float4*)(out + base) = o4;
}

// ======================= launch =======================
extern "C" void kernel_launch(void* const* d_in, const int* in_sizes, int n_in,
                              void* d_out, int out_size) {
    const float* x    = (const float*)d_in[0];
    const int*   chain= (const int*)  d_in[1];
    const float* W3   = (const float*)d_in[2];
    const float* b3   = (const float*)d_in[3];
    const float* W5   = (const float*)d_in[4];
    const float* b5   = (const float*)d_in[5];
    const float* W7   = (const float*)d_in[6];
    const float* b7   = (const float*)d_in[7];
    const float* w1   = (const float*)d_in[8];
    const float* bm1  = (const float*)d_in[9];
    const float* w2   = (const float*)d_in[10];
    const float* bm2  = (const float*)d_in[11];
    const float* g1   = (const float*)d_in[12];
    const float* be1  = (const float*)d_in[13];
    const float* g2   = (const float*)d_in[14];
    const float* be2  = (const float*)d_in[15];
    float* out = (float*)d_out;

    __half *xa, *c1, *c2, *hh, *t, *wc, *w1p, *w2p;
    float *hf, *mlpf;
    cudaGetSymbolAddress((void**)&xa, g_xa);
    cudaGetSymbolAddress((void**)&c1, g_c1);
    cudaGetSymbolAddress((void**)&c2, g_c2);
    cudaGetSymbolAddress((void**)&hh, g_hh);
    cudaGetSymbolAddress((void**)&hf, g_hf);
    cudaGetSymbolAddress((void**)&t,  g_t);
    cudaGetSymbolAddress((void**)&mlpf, g_mlp);
    cudaGetSymbolAddress((void**)&wc,  g_wc);
    cudaGetSymbolAddress((void**)&w1p, g_w1);
    cudaGetSymbolAddress((void**)&w2p, g_w2);

    const int SMEMSZ = 3 * 2 * 128 * 136 * 2;   // 208896 B
    cudaFuncSetAttribute(gemm_mma<0,3,DQ,DQ>,  cudaFuncAttributeMaxDynamicSharedMemorySize, SMEMSZ);
    cudaFuncSetAttribute(gemm_mma<0,5,DQ,DQ>,  cudaFuncAttributeMaxDynamicSharedMemorySize, SMEMSZ);
    cudaFuncSetAttribute(gemm_mma<0,7,DQ,DQ>,  cudaFuncAttributeMaxDynamicSharedMemorySize, SMEMSZ);
    cudaFuncSetAttribute(gemm_mma<1,1,DQ,D4Q>, cudaFuncAttributeMaxDynamicSharedMemorySize, SMEMSZ);
    cudaFuncSetAttribute(gemm_mma<2,1,D4Q,DQ>, cudaFuncAttributeMaxDynamicSharedMemorySize, SMEMSZ);

    // prep
    prep_conv<<<(DQ*DQ*3 + 255)/256, 256>>>(W3, wc,           3);
    prep_conv<<<(DQ*DQ*5 + 255)/256, 256>>>(W5, wc + 3*DQ*DQ, 5);
    prep_conv<<<(DQ*DQ*7 + 255)/256, 256>>>(W7, wc + 8*DQ*DQ, 7);
    prep_w1<<<(DQ*D4Q + 255)/256, 256>>>(w1, w1p);
    prep_w2<<<(D4Q*DQ + 255)/256, 256>>>(w2, w2p);
    convert_x<<<(MQ*DQ/4 + 255)/256, 256>>>(x, xa);

    // conv chain
    dim3 cgrid(LQ/128, DQ/128, BQ);
    gemm_mma<0,3,DQ,DQ><<<cgrid, 256, SMEMSZ>>>(xa, chain, wc,           b3, nullptr, c1);
    gemm_mma<0,5,DQ,DQ><<<cgrid, 256, SMEMSZ>>>(c1, chain, wc + 3*DQ*DQ, b5, nullptr, c2);
    gemm_mma<0,7,DQ,DQ><<<cgrid, 256, SMEMSZ>>>(c2, chain, wc + 8*DQ*DQ, b7, nullptr, c1);

    // h = LN1(x + conv)
    ln1_kernel<<<MQ, 128>>>(x, c1, g1, be1, hh, hf);

    // MLP
    gemm_mma<1,1,DQ,D4Q><<<dim3(MQ/128, D4Q/128, 1), 256, SMEMSZ>>>(hh, nullptr, w1p, bm1, nullptr, t);
    gemm_mma<2,1,D4Q,DQ><<<dim3(MQ/128, DQ/128, 1),  256, SMEMSZ>>>(t,  nullptr, w2p, bm2, mlpf, nullptr);

    // out = LN2(h + mlp)
    ln2_kernel<<<MQ, 128>>>(hf, mlpf, g2, be2, out);
}